// round 9
// baseline (speedup 1.0000x reference)
#include <cuda_runtime.h>
#include <cuda_fp16.h>
#include <math.h>
#include <stdint.h>

#define B_ROWS 16384
#define D_DIM  2048
#define D_HALF 1024
#define S_PROTO 64
#define KCOMB  (D_DIM + S_PROTO)   // 2112

// ---------------------------------------------------------------------------
// Scratch (device globals; allocation-free per harness rules)
// ---------------------------------------------------------------------------
__device__ __half g_x_h[(size_t)B_ROWS * D_DIM];
__device__ __half g_Win_h[(size_t)D_DIM * D_DIM];
__device__ __half g_Wr1_h[(size_t)D_HALF * D_DIM];
__device__ __half g_wcomb[(size_t)D_DIM * KCOMB];      // [W_out1 | P2^T] fp16
__device__ __half g_attn_h[(size_t)B_ROWS * S_PROTO];
__device__ __half g_r_h[(size_t)B_ROWS * D_HALF];      // r in fp16
__device__ __half g_qp_h[(size_t)S_PROTO * D_DIM];     // q = pn @ W_in, fp16
__device__ float g_pn_f[(size_t)S_PROTO * D_DIM];      // normalized protos fp32
__device__ float g_p2part[4 * S_PROTO * D_DIM];
__device__ float g_qppart[8 * S_PROTO * D_DIM];
__device__ float g_ssqpart[16 * B_ROWS];               // per n-tile row ssq
__device__ float g_invn[B_ROWS];
__device__ float g_tw[(size_t)B_ROWS * 4];
__device__ float g_base[S_PROTO];
__device__ float g_wsimc[S_PROTO];

// ---------------------------------------------------------------------------
// PTX helpers (baseline ISA: mma.sync / ldmatrix / cp.async)
// ---------------------------------------------------------------------------
__device__ __forceinline__ uint32_t smem_to_u32(const void* p) {
    uint32_t a;
    asm("{ .reg .u64 t; cvta.to.shared.u64 t, %1; cvt.u32.u64 %0, t; }"
        : "=r"(a) : "l"(p));
    return a;
}

__device__ __forceinline__ void cpasync16(uint32_t saddr, const void* g) {
    asm volatile("cp.async.cg.shared.global [%0], [%1], 16;"
                 :: "r"(saddr), "l"(g));
}
#define CP_COMMIT() asm volatile("cp.async.commit_group;" ::: "memory")
#define CP_WAIT(n)  asm volatile("cp.async.wait_group %0;" :: "n"(n) : "memory")

__device__ __forceinline__ void ldsm4(uint32_t* r, uint32_t addr) {
    asm volatile("ldmatrix.sync.aligned.m8n8.x4.shared.b16 {%0,%1,%2,%3}, [%4];"
                 : "=r"(r[0]), "=r"(r[1]), "=r"(r[2]), "=r"(r[3]) : "r"(addr));
}

__device__ __forceinline__ void mma_f16(float* d, const uint32_t* a, const uint32_t* b) {
    asm volatile(
        "mma.sync.aligned.m16n8k16.row.col.f32.f16.f16.f32 "
        "{%0,%1,%2,%3}, {%4,%5,%6,%7}, {%8,%9}, {%0,%1,%2,%3};"
        : "+f"(d[0]), "+f"(d[1]), "+f"(d[2]), "+f"(d[3])
        : "r"(a[0]), "r"(a[1]), "r"(a[2]), "r"(a[3]), "r"(b[0]), "r"(b[1]));
}

// ---------------------------------------------------------------------------
// Misc helpers
// ---------------------------------------------------------------------------
__device__ __forceinline__ float gelu_exact(float v) {
    return 0.5f * v * (1.0f + erff(v * 0.70710678118654752440f));
}

__device__ __forceinline__ float block_reduce_sum(float v) {
    __shared__ float sh[32];
    int lane = threadIdx.x & 31, w = threadIdx.x >> 5;
    #pragma unroll
    for (int o = 16; o; o >>= 1) v += __shfl_xor_sync(0xFFFFFFFFu, v, o);
    if (lane == 0) sh[w] = v;
    __syncthreads();
    float r = (threadIdx.x < (blockDim.x >> 5)) ? sh[threadIdx.x] : 0.0f;
    if (w == 0) {
        #pragma unroll
        for (int o = 16; o; o >>= 1) r += __shfl_xor_sync(0xFFFFFFFFu, r, o);
        if (lane == 0) sh[0] = r;
    }
    __syncthreads();
    float out = sh[0];
    __syncthreads();
    return out;
}

// ---------------------------------------------------------------------------
// fp32 -> fp16 convert (vectorized, contiguous)
// ---------------------------------------------------------------------------
__global__ void tohalf_kernel(const float* __restrict__ s,
                              __half* __restrict__ d, size_t n4)
{
    size_t i = (size_t)blockIdx.x * blockDim.x + threadIdx.x;
    if (i >= n4) return;
    float4 v = reinterpret_cast<const float4*>(s)[i];
    __half2 h0 = __floats2half2_rn(v.x, v.y);
    __half2 h1 = __floats2half2_rn(v.z, v.w);
    uint2 o;
    o.x = *reinterpret_cast<uint32_t*>(&h0);
    o.y = *reinterpret_cast<uint32_t*>(&h1);
    reinterpret_cast<uint2*>(d)[i] = o;
}

// ---------------------------------------------------------------------------
// Pack W_out[:, 0:2048] (stride 4096) into wcomb[:, 0:2048] (stride 2112) fp16
// ---------------------------------------------------------------------------
__global__ void wout1_pack_kernel(const float* __restrict__ wout,
                                  __half* __restrict__ wcomb)
{
    int idx = blockIdx.x * 256 + threadIdx.x;
    int row = idx >> 9;
    int c4  = idx & 511;
    float4 v = *reinterpret_cast<const float4*>(wout + (size_t)row * 2 * D_DIM + c4 * 4);
    __half2 h0 = __floats2half2_rn(v.x, v.y);
    __half2 h1 = __floats2half2_rn(v.z, v.w);
    uint2 o;
    o.x = *reinterpret_cast<uint32_t*>(&h0);
    o.y = *reinterpret_cast<uint32_t*>(&h1);
    *reinterpret_cast<uint2*>(wcomb + (size_t)row * KCOMB + c4 * 4) = o;
}

// ---------------------------------------------------------------------------
// P2 partials (k-split, conflict-free transposed tiles):
//   part[ks][s][n] = sum_{k in slice} protos[s][k] * W_out[n][2048+k]
// grid = (16, 4), 256 threads.
// ---------------------------------------------------------------------------
__global__ void __launch_bounds__(256)
p2_kernel(const float* __restrict__ protos, const float* __restrict__ wout,
          float* __restrict__ part)
{
    constexpr int BKC = 32;
    __shared__ float Pt[BKC][68];
    __shared__ float Wt[BKC][132];

    const int tid = threadIdx.x;
    const int n0 = blockIdx.x * 128;
    const int kb = blockIdx.y * 512;
    const int tr = tid >> 4;
    const int tc = tid & 15;

    float acc[4][8];
    #pragma unroll
    for (int i = 0; i < 4; i++)
        #pragma unroll
        for (int j = 0; j < 8; j++) acc[i][j] = 0.0f;

    for (int kt = 0; kt < 512; kt += BKC) {
        #pragma unroll
        for (int i = 0; i < 2; i++) {
            int idx = tid + i * 256;
            int s = idx >> 3, kq = (idx & 7) * 4;
            float4 v = *reinterpret_cast<const float4*>(
                protos + (size_t)s * D_DIM + kb + kt + kq);
            Pt[kq+0][s] = v.x; Pt[kq+1][s] = v.y;
            Pt[kq+2][s] = v.z; Pt[kq+3][s] = v.w;
        }
        #pragma unroll
        for (int i = 0; i < 4; i++) {
            int idx = tid + i * 256;
            int n = idx >> 3, kq = (idx & 7) * 4;
            float4 v = *reinterpret_cast<const float4*>(
                wout + (size_t)(n0 + n) * 2 * D_DIM + D_DIM + kb + kt + kq);
            Wt[kq+0][n] = v.x; Wt[kq+1][n] = v.y;
            Wt[kq+2][n] = v.z; Wt[kq+3][n] = v.w;
        }
        __syncthreads();
        #pragma unroll 8
        for (int k = 0; k < BKC; k++) {
            float4 p  = *reinterpret_cast<const float4*>(&Pt[k][tr * 4]);
            float4 wa = *reinterpret_cast<const float4*>(&Wt[k][tc * 8]);
            float4 wb = *reinterpret_cast<const float4*>(&Wt[k][tc * 8 + 4]);
            float pv[4] = {p.x, p.y, p.z, p.w};
            float wv[8] = {wa.x, wa.y, wa.z, wa.w, wb.x, wb.y, wb.z, wb.w};
            #pragma unroll
            for (int i = 0; i < 4; i++)
                #pragma unroll
                for (int j = 0; j < 8; j++)
                    acc[i][j] = fmaf(pv[i], wv[j], acc[i][j]);
        }
        __syncthreads();
    }

    float* dst = part + (size_t)blockIdx.y * S_PROTO * D_DIM;
    #pragma unroll
    for (int i = 0; i < 4; i++)
        #pragma unroll
        for (int j = 0; j < 8; j++)
            dst[(size_t)(tr * 4 + i) * D_DIM + n0 + tc * 8 + j] = acc[i][j];
}

__global__ void p2_reduce_kernel(const float* __restrict__ part,
                                 __half* __restrict__ wcomb)
{
    int idx = blockIdx.x * 256 + threadIdx.x;
    int s = idx >> 11;
    int n = idx & 2047;
    size_t o = (size_t)s * D_DIM + n;
    float v = part[o] + part[o + S_PROTO * D_DIM]
            + part[o + 2 * S_PROTO * D_DIM] + part[o + 3 * S_PROTO * D_DIM];
    wcomb[(size_t)n * KCOMB + D_DIM + s] = __float2half_rn(v);
}

// ---------------------------------------------------------------------------
// qp partials: part[ks][s][d] = sum_{j in slice} pn[s][j] * Win[j][d]
// grid = (16 d-tiles, 8 j-slices of 256), 256 threads.
// ---------------------------------------------------------------------------
__global__ void __launch_bounds__(256)
qp_kernel(const float* __restrict__ pnf, const float* __restrict__ win,
          float* __restrict__ part)
{
    constexpr int BKC = 32;
    __shared__ float Pt[BKC][68];
    __shared__ float Wt[BKC][132];

    const int tid = threadIdx.x;
    const int n0 = blockIdx.x * 128;         // d tile
    const int kb = blockIdx.y * 256;         // j slice
    const int tr = tid >> 4;
    const int tc = tid & 15;

    float acc[4][8];
    #pragma unroll
    for (int i = 0; i < 4; i++)
        #pragma unroll
        for (int j = 0; j < 8; j++) acc[i][j] = 0.0f;

    for (int kt = 0; kt < 256; kt += BKC) {
        #pragma unroll
        for (int i = 0; i < 2; i++) {
            int idx = tid + i * 256;
            int s = idx >> 3, jq = (idx & 7) * 4;
            float4 v = *reinterpret_cast<const float4*>(
                pnf + (size_t)s * D_DIM + kb + kt + jq);
            Pt[jq+0][s] = v.x; Pt[jq+1][s] = v.y;
            Pt[jq+2][s] = v.z; Pt[jq+3][s] = v.w;
        }
        #pragma unroll
        for (int i = 0; i < 4; i++) {
            int idx = tid + i * 256;
            int j = idx >> 5, d4 = idx & 31;      // Win rows: d contiguous
            float4 v = *reinterpret_cast<const float4*>(
                win + (size_t)(kb + kt + j) * D_DIM + n0 + d4 * 4);
            Wt[j][d4*4+0] = v.x; Wt[j][d4*4+1] = v.y;
            Wt[j][d4*4+2] = v.z; Wt[j][d4*4+3] = v.w;
        }
        __syncthreads();
        #pragma unroll 8
        for (int k = 0; k < BKC; k++) {
            float4 p  = *reinterpret_cast<const float4*>(&Pt[k][tr * 4]);
            float4 wa = *reinterpret_cast<const float4*>(&Wt[k][tc * 8]);
            float4 wb = *reinterpret_cast<const float4*>(&Wt[k][tc * 8 + 4]);
            float pv[4] = {p.x, p.y, p.z, p.w};
            float wv[8] = {wa.x, wa.y, wa.z, wa.w, wb.x, wb.y, wb.z, wb.w};
            #pragma unroll
            for (int i = 0; i < 4; i++)
                #pragma unroll
                for (int j = 0; j < 8; j++)
                    acc[i][j] = fmaf(pv[i], wv[j], acc[i][j]);
        }
        __syncthreads();
    }

    float* dst = part + (size_t)blockIdx.y * S_PROTO * D_DIM;
    #pragma unroll
    for (int i = 0; i < 4; i++)
        #pragma unroll
        for (int j = 0; j < 8; j++)
            dst[(size_t)(tr * 4 + i) * D_DIM + n0 + tc * 8 + j] = acc[i][j];
}

__global__ void qp_reduce_kernel(const float* __restrict__ part,
                                 __half* __restrict__ qph)
{
    int idx = blockIdx.x * 256 + threadIdx.x;   // over 64*2048
    float v = 0.0f;
    #pragma unroll
    for (int t = 0; t < 8; t++) v += part[(size_t)t * S_PROTO * D_DIM + idx];
    qph[idx] = __float2half_rn(v);
}

// ---------------------------------------------------------------------------
// ssq combine: invn[row] = 1 / max(sqrt(sum_16 tiles), 1e-12)
// ---------------------------------------------------------------------------
__global__ void ssq_combine_kernel(const float* __restrict__ part,
                                   float* __restrict__ invn)
{
    int row = blockIdx.x * 256 + threadIdx.x;
    float s = 0.0f;
    #pragma unroll
    for (int t = 0; t < 16; t++) s += part[(size_t)t * B_ROWS + row];
    invn[row] = 1.0f / fmaxf(sqrtf(s), 1e-12f);
}

// ---------------------------------------------------------------------------
// Single-pass fp16 HMMA GEMM.
// MODE bits: 1=gelu, 2=+Xres(fp32), 4=split-A, 8=dual-output (second gelued),
//            16=fp16 outputs, 32=first-output is row-ssq (no C write).
// BM=BN=128, BK=64, 3-stage cp.async, 256 threads, 2 CTAs/SM.
// ---------------------------------------------------------------------------
template<int MODE>
__global__ void __launch_bounds__(256, 2)
mma_gemm(const __half* __restrict__ A, const __half* __restrict__ A2,
         const __half* __restrict__ Bm,
         const float* __restrict__ bias, const float* __restrict__ Xres,
         void* __restrict__ C, int N, int K, int Ksplit,
         int strideA, int strideA2,
         const __half* __restrict__ B2,
         const float* __restrict__ bias2, void* __restrict__ C2,
         int N2, int NXtiles, float* __restrict__ ssqpart)
{
    constexpr int BM = 128, BK = 64, STAGES = 3;
    constexpr int TILE_B  = BM * BK * 2;
    constexpr int STAGE_B = 2 * TILE_B;

    extern __shared__ __align__(16) char smem[];
    const uint32_t sbase = smem_to_u32(smem);

    const int tid  = threadIdx.x;
    const int wid  = tid >> 5, lane = tid & 31;
    const int m0 = blockIdx.y * BM;

    int bx = blockIdx.x;
    bool second = false;
    if constexpr (MODE & 8) {
        if (bx >= NXtiles) { second = true; bx -= NXtiles; }
    }
    const __half* pB = second ? B2 : Bm;
    const float* pbias = second ? bias2 : bias;
    void* pC = second ? C2 : C;
    const int NN = second ? N2 : N;
    const int n0 = bx * BM;
    const bool do_gelu = (MODE & 1) || second;

    const int wm = (wid >> 2) * 64;
    const int wn = (wid & 3) * 32;

    float acc[4][4][4];
    #pragma unroll
    for (int i = 0; i < 4; i++)
        #pragma unroll
        for (int j = 0; j < 4; j++)
            #pragma unroll
            for (int k = 0; k < 4; k++) acc[i][j][k] = 0.0f;

    const int nk = K / BK;

    auto load_stage = [&](int s, int t) {
        const int k0 = t * BK;
        const __half* pA = A;
        int ka = k0, sA = strideA;
        if constexpr (MODE & 4) {
            if (k0 >= Ksplit) { pA = A2; ka = k0 - Ksplit; sA = strideA2; }
        }
        const uint32_t sb = sbase + s * STAGE_B;
        #pragma unroll
        for (int i = 0; i < 4; i++) {
            int idx = tid + i * 256;
            int row = idx >> 3, g = idx & 7;
            int gs  = g ^ (row & 7);
            uint32_t so = row * 128 + gs * 16;
            size_t ga = (size_t)(m0 + row) * sA + ka + g * 8;
            size_t gb = (size_t)(n0 + row) * K + k0 + g * 8;
            cpasync16(sb + so, pA + ga);
            cpasync16(sb + TILE_B + so, pB + gb);
        }
    };

    auto compute_stage = [&](int s) {
        const uint32_t sb = sbase + s * STAGE_B;
        #pragma unroll
        for (int ks = 0; ks < 4; ks++) {
            uint32_t afr[4][4], bfr[2][4];
            #pragma unroll
            for (int mf = 0; mf < 4; mf++) {
                int row = wm + mf * 16 + (lane & 15);
                int g   = ks * 2 + (lane >> 4);
                ldsm4(afr[mf], sb + row * 128 + ((g ^ (row & 7)) * 16));
            }
            #pragma unroll
            for (int nf2 = 0; nf2 < 2; nf2++) {
                int nrow = wn + nf2 * 16 + ((lane >> 4) & 1) * 8 + (lane & 7);
                int g    = ks * 2 + ((lane >> 3) & 1);
                ldsm4(bfr[nf2], sb + TILE_B + nrow * 128 + ((g ^ (nrow & 7)) * 16));
            }
            #pragma unroll
            for (int mf = 0; mf < 4; mf++)
                #pragma unroll
                for (int nf = 0; nf < 4; nf++)
                    mma_f16(acc[mf][nf], afr[mf], &bfr[nf >> 1][(nf & 1) * 2]);
        }
    };

    load_stage(0, 0); CP_COMMIT();
    load_stage(1, 1); CP_COMMIT();

    for (int t = 0; t < nk; t++) {
        CP_WAIT(STAGES - 2);
        __syncthreads();
        if (t + STAGES - 1 < nk) load_stage((t + STAGES - 1) % STAGES, t + STAGES - 1);
        CP_COMMIT();
        compute_stage(t % STAGES);
    }

    bool ssq_mode = false;
    if constexpr (MODE & 32) ssq_mode = !second;

    if (ssq_mode) {
        // per-thread sum of squares over its 8 cols for 8 rows
        float rs[4][2];
        #pragma unroll
        for (int mf = 0; mf < 4; mf++)
            #pragma unroll
            for (int half = 0; half < 2; half++) {
                float s = 0.0f;
                #pragma unroll
                for (int nf = 0; nf < 4; nf++)
                    #pragma unroll
                    for (int k = 0; k < 2; k++) {
                        int col = n0 + wn + nf * 8 + (lane & 3) * 2 + k;
                        float v = acc[mf][nf][half * 2 + k] + pbias[col];
                        s = fmaf(v, v, s);
                    }
                rs[mf][half] = s;
            }
        #pragma unroll
        for (int mf = 0; mf < 4; mf++)
            #pragma unroll
            for (int half = 0; half < 2; half++) {
                rs[mf][half] += __shfl_xor_sync(0xFFFFFFFFu, rs[mf][half], 1);
                rs[mf][half] += __shfl_xor_sync(0xFFFFFFFFu, rs[mf][half], 2);
            }
        __syncthreads();   // stage smem no longer needed
        float* ssqsm = reinterpret_cast<float*>(smem);
        if ((lane & 3) == 0) {
            #pragma unroll
            for (int mf = 0; mf < 4; mf++)
                #pragma unroll
                for (int half = 0; half < 2; half++)
                    ssqsm[wid * 64 + mf * 16 + (lane >> 2) + half * 8] = rs[mf][half];
        }
        __syncthreads();
        if (tid < 128) {
            int group = tid >> 6, r = tid & 63;
            float v = ssqsm[(group * 4 + 0) * 64 + r]
                    + ssqsm[(group * 4 + 1) * 64 + r]
                    + ssqsm[(group * 4 + 2) * 64 + r]
                    + ssqsm[(group * 4 + 3) * 64 + r];
            ssqpart[(size_t)bx * B_ROWS + m0 + group * 64 + r] = v;
        }
    } else {
        #pragma unroll
        for (int mf = 0; mf < 4; mf++)
            #pragma unroll
            for (int nf = 0; nf < 4; nf++)
                #pragma unroll
                for (int half = 0; half < 2; half++) {
                    int row = m0 + wm + mf * 16 + (lane >> 2) + half * 8;
                    int col = n0 + wn + nf * 8 + (lane & 3) * 2;
                    float v0 = acc[mf][nf][half * 2 + 0] + pbias[col];
                    float v1 = acc[mf][nf][half * 2 + 1] + pbias[col + 1];
                    if (do_gelu) { v0 = gelu_exact(v0); v1 = gelu_exact(v1); }
                    if constexpr (MODE & 2) {
                        float2 xr = *reinterpret_cast<const float2*>(
                            &Xres[(size_t)row * NN + col]);
                        v0 += xr.x; v1 += xr.y;
                    }
                    if constexpr (MODE & 16) {
                        __half2 o = __floats2half2_rn(v0, v1);
                        *reinterpret_cast<__half2*>(
                            (__half*)pC + (size_t)row * NN + col) = o;
                    } else {
                        float2 o; o.x = v0; o.y = v1;
                        *reinterpret_cast<float2*>(
                            (float*)pC + (size_t)row * NN + col) = o;
                    }
                }
    }
}

// ---------------------------------------------------------------------------
// sim_attn v3: HMMA sim (fp16 x @ fp16 qp^T) + invn + salience + softmax
// -> attn fp16. 128 rows/block, 256 threads.
// ---------------------------------------------------------------------------
__global__ void __launch_bounds__(256)
sim_attn_kernel(const __half* __restrict__ X, const __half* __restrict__ QP,
                const float* __restrict__ tw, const float* __restrict__ invn_g,
                __half* __restrict__ attn)
{
    constexpr int BK = 64;
    constexpr int H_B  = 128 * BK * 2;
    constexpr int PN_B = S_PROTO * BK * 2;
    constexpr int STAGE_B = H_B + PN_B;

    extern __shared__ __align__(16) char dsm[];
    const uint32_t sbase = smem_to_u32(dsm);
    float* sal = reinterpret_cast<float*>(dsm);

    const int tid = threadIdx.x;
    const int wid = tid >> 5, lane = tid & 31;
    const int m0 = blockIdx.x * 128;
    const int K = D_DIM;

    float acc[8][4];
    #pragma unroll
    for (int i = 0; i < 8; i++)
        #pragma unroll
        for (int j = 0; j < 4; j++) acc[i][j] = 0.0f;

    uint4 hReg[4]; uint4 pReg[2];

    auto fetch = [&](int t) {
        const int k0 = t * BK;
        #pragma unroll
        for (int i = 0; i < 4; i++) {
            int idx = tid + i * 256;
            int row = idx >> 3, g = idx & 7;
            hReg[i] = *reinterpret_cast<const uint4*>(
                X + (size_t)(m0 + row) * K + k0 + g * 8);
        }
        #pragma unroll
        for (int i = 0; i < 2; i++) {
            int idx = tid + i * 256;
            int s = idx >> 3, g = idx & 7;
            pReg[i] = *reinterpret_cast<const uint4*>(
                QP + (size_t)s * K + k0 + g * 8);
        }
    };
    auto stash = [&](int buf) {
        char* cb = dsm + buf * STAGE_B;
        #pragma unroll
        for (int i = 0; i < 4; i++) {
            int idx = tid + i * 256;
            int row = idx >> 3, g = idx & 7;
            *reinterpret_cast<uint4*>(cb + row * 128 + ((g ^ (row & 7)) * 16)) = hReg[i];
        }
        #pragma unroll
        for (int i = 0; i < 2; i++) {
            int idx = tid + i * 256;
            int s = idx >> 3, g = idx & 7;
            *reinterpret_cast<uint4*>(cb + H_B + s * 128 + ((g ^ (s & 7)) * 16)) = pReg[i];
        }
    };
    auto compute = [&](int buf) {
        const uint32_t sb = sbase + buf * STAGE_B;
        #pragma unroll
        for (int ks = 0; ks < 4; ks++) {
            uint32_t afr[4], bfr[4][4];
            {
                int row = wid * 16 + (lane & 15);
                int g   = ks * 2 + (lane >> 4);
                ldsm4(afr, sb + row * 128 + ((g ^ (row & 7)) * 16));
            }
            #pragma unroll
            for (int nf2 = 0; nf2 < 4; nf2++) {
                int nrow = nf2 * 16 + ((lane >> 4) & 1) * 8 + (lane & 7);
                int g    = ks * 2 + ((lane >> 3) & 1);
                ldsm4(bfr[nf2], sb + H_B + nrow * 128 + ((g ^ (nrow & 7)) * 16));
            }
            #pragma unroll
            for (int nf = 0; nf < 8; nf++)
                mma_f16(acc[nf], afr, &bfr[nf >> 1][(nf & 1) * 2]);
        }
    };

    const int nk = K / BK;
    fetch(0); stash(0);
    __syncthreads();
    for (int t = 0; t < nk; t++) {
        const int cur = t & 1;
        if (t + 1 < nk) fetch(t + 1);
        compute(cur);
        if (t + 1 < nk) stash(cur ^ 1);
        __syncthreads();
    }

    // salience into smem (overlay; all compute done after last sync)
    {
        int r0 = wid * 16 + (lane >> 2);
        #pragma unroll
        for (int half = 0; half < 2; half++) {
            int row = r0 + half * 8;
            float invn = invn_g[m0 + row];
            #pragma unroll
            for (int nf = 0; nf < 8; nf++) {
                int col = nf * 8 + (lane & 3) * 2;
                float twv = tw[(size_t)(m0 + row) * 4 + (col >> 4)];
                float v0 = g_wsimc[col] * twv * (acc[nf][half*2+0] * invn) + g_base[col];
                float twv1 = tw[(size_t)(m0 + row) * 4 + ((col + 1) >> 4)];
                float v1 = g_wsimc[col+1] * twv1 * (acc[nf][half*2+1] * invn) + g_base[col+1];
                sal[row * 65 + col]     = fminf(fmaxf(v0, 0.0f), 1.0f);
                sal[row * 65 + col + 1] = fminf(fmaxf(v1, 0.0f), 1.0f);
            }
        }
    }
    __syncthreads();

    // softmax over 64 per row; 2 threads per row
    {
        int row = tid >> 1, half = tid & 1;
        const float* srow = &sal[row * 65 + half * 32];
        float m = -1e30f;
        #pragma unroll
        for (int c = 0; c < 32; c++) m = fmaxf(m, srow[c]);
        m = fmaxf(m, __shfl_xor_sync(0xFFFFFFFFu, m, 1));
        const float invT = 1.0f / 0.07f;
        float e[32], s = 0.0f;
        #pragma unroll
        for (int c = 0; c < 32; c++) { e[c] = expf((srow[c] - m) * invT); s += e[c]; }
        s += __shfl_xor_sync(0xFFFFFFFFu, s, 1);
        float inv = 1.0f / s;
        __half* dst = &attn[(size_t)(m0 + row) * S_PROTO + half * 32];
        #pragma unroll
        for (int c = 0; c < 32; c += 2) {
            __half2 o = __floats2half2_rn(e[c] * inv, e[c+1] * inv);
            *reinterpret_cast<__half2*>(dst + c) = o;
        }
    }
}

// ---------------------------------------------------------------------------
// Prototype prep: normalized protos -> fp32, plus static salience terms
// ---------------------------------------------------------------------------
__global__ void proto_prep(const float* __restrict__ protos,
                           const float* __restrict__ conf,
                           const float* __restrict__ age,
                           const float* __restrict__ ev,
                           float* __restrict__ pn_f)
{
    const int s = blockIdx.x;
    float ss = 0.0f;
    for (int k = threadIdx.x; k < D_DIM; k += 256) {
        float v = protos[(size_t)s * D_DIM + k];
        ss += v * v;
    }
    float tot = block_reduce_sum(ss);
    float scale = 1.0f / fmaxf(sqrtf(tot), 1e-12f);
    for (int k = threadIdx.x; k < D_DIM; k += 256)
        pn_f[(size_t)s * D_DIM + k] = protos[(size_t)s * D_DIM + k] * scale;

    if (threadIdx.x == 0) {
        float evmax = 0.0f;
        for (int i = 0; i < S_PROTO; i++) evmax = fmaxf(evmax, ev[i]);
        float freq = logf(ev[s] + 1.0f) / (logf(evmax + 2.0f) + 1e-8f);
        float rec  = expf(-age[s] * (1.0f / 200.0f));
        g_base[s]  = 0.2f * rec + 0.15f * freq + 0.1f * conf[s] + 0.1f * 0.9f;
        g_wsimc[s] = 0.45f * conf[s];
    }
}

// ---------------------------------------------------------------------------
// Type weights softmax (4 logits), r in fp16. 1 warp per row.
// ---------------------------------------------------------------------------
__global__ void type_weights_kernel(const __half* __restrict__ r,
                                    const float* __restrict__ Wr2,
                                    const float* __restrict__ br2,
                                    float* __restrict__ tw)
{
    const int warp = threadIdx.x >> 5, lane = threadIdx.x & 31;
    const int b = blockIdx.x * 8 + warp;
    const uint4* rp = reinterpret_cast<const uint4*>(r + (size_t)b * D_HALF);
    float acc[4] = {0.f, 0.f, 0.f, 0.f};
    for (int i = lane; i < D_HALF / 8; i += 32) {
        uint4 rv = rp[i];
        float rf[8];
        #pragma unroll
        for (int q = 0; q < 4; q++) {
            __half2 hv = *reinterpret_cast<__half2*>(
                reinterpret_cast<uint32_t*>(&rv) + q);
            float2 f = __half22float2(hv);
            rf[q*2] = f.x; rf[q*2+1] = f.y;
        }
        #pragma unroll
        for (int t = 0; t < 4; t++) {
            const float* wr = Wr2 + (size_t)t * D_HALF + i * 8;
            float4 w0 = *reinterpret_cast<const float4*>(wr);
            float4 w1 = *reinterpret_cast<const float4*>(wr + 4);
            acc[t] += rf[0]*w0.x + rf[1]*w0.y + rf[2]*w0.z + rf[3]*w0.w
                    + rf[4]*w1.x + rf[5]*w1.y + rf[6]*w1.z + rf[7]*w1.w;
        }
    }
    #pragma unroll
    for (int t = 0; t < 4; t++)
        #pragma unroll
        for (int o = 16; o; o >>= 1)
            acc[t] += __shfl_xor_sync(0xFFFFFFFFu, acc[t], o);
    if (lane == 0) {
        float z[4], m = -1e30f;
        #pragma unroll
        for (int t = 0; t < 4; t++) { z[t] = acc[t] + br2[t]; m = fmaxf(m, z[t]); }
        float s = 0.0f;
        #pragma unroll
        for (int t = 0; t < 4; t++) { z[t] = expf(z[t] - m); s += z[t]; }
        float inv = 1.0f / s;
        #pragma unroll
        for (int t = 0; t < 4; t++) tw[(size_t)b * 4 + t] = z[t] * inv;
    }
}

// ---------------------------------------------------------------------------
// In-place LayerNorm over D
// ---------------------------------------------------------------------------
__global__ void layernorm_inplace(float* __restrict__ y,
                                  const float* __restrict__ w,
                                  const float* __restrict__ bb)
{
    const size_t base = (size_t)blockIdx.x * D_DIM;
    float4* yp = reinterpret_cast<float4*>(y + base);
    float4 v[2];
    float sum = 0.0f;
    #pragma unroll
    for (int i = 0; i < 2; i++) {
        v[i] = yp[threadIdx.x + 256 * i];
        sum += v[i].x + v[i].y + v[i].z + v[i].w;
    }
    float mu = block_reduce_sum(sum) * (1.0f / D_DIM);
    float sq = 0.0f;
    #pragma unroll
    for (int i = 0; i < 2; i++) {
        float dx = v[i].x - mu, dy = v[i].y - mu, dz = v[i].z - mu, dw = v[i].w - mu;
        sq += dx*dx + dy*dy + dz*dz + dw*dw;
    }
    float var = block_reduce_sum(sq) * (1.0f / D_DIM);
    float rstd = rsqrtf(var + 1e-5f);
    #pragma unroll
    for (int i = 0; i < 2; i++) {
        int col = (threadIdx.x + 256 * i) * 4;
        float4 wv = *reinterpret_cast<const float4*>(&w[col]);
        float4 bv = *reinterpret_cast<const float4*>(&bb[col]);
        float4 o;
        o.x = wv.x * (v[i].x - mu) * rstd + bv.x;
        o.y = wv.y * (v[i].y - mu) * rstd + bv.y;
        o.z = wv.z * (v[i].z - mu) * rstd + bv.z;
        o.w = wv.w * (v[i].w - mu) * rstd + bv.w;
        yp[threadIdx.x + 256 * i] = o;
    }
}

// ---------------------------------------------------------------------------
// Launch
// ---------------------------------------------------------------------------
extern "C" void kernel_launch(void* const* d_in, const int* in_sizes, int n_in,
                              void* d_out, int out_size)
{
    const float* x      = (const float*)d_in[0];
    const float* protos = (const float*)d_in[1];
    const float* conf   = (const float*)d_in[2];
    const float* age    = (const float*)d_in[3];
    const float* ev     = (const float*)d_in[4];
    const float* W_in   = (const float*)d_in[5];
    const float* b_in   = (const float*)d_in[6];
    const float* Wr1    = (const float*)d_in[7];
    const float* br1    = (const float*)d_in[8];
    const float* Wr2    = (const float*)d_in[9];
    const float* br2    = (const float*)d_in[10];
    const float* W_out  = (const float*)d_in[11];
    const float* b_out  = (const float*)d_in[12];
    const float* ln_w   = (const float*)d_in[13];
    const float* ln_b   = (const float*)d_in[14];
    float* out = (float*)d_out;

    __half *xh, *winh, *wr1h, *wcomb, *attnh, *rh, *qph;
    float *tw, *p2part, *qppart, *pnf, *ssqpart, *invn;
    cudaGetSymbolAddress((void**)&xh,    g_x_h);
    cudaGetSymbolAddress((void**)&winh,  g_Win_h);
    cudaGetSymbolAddress((void**)&wr1h,  g_Wr1_h);
    cudaGetSymbolAddress((void**)&wcomb, g_wcomb);
    cudaGetSymbolAddress((void**)&attnh, g_attn_h);
    cudaGetSymbolAddress((void**)&rh,    g_r_h);
    cudaGetSymbolAddress((void**)&qph,   g_qp_h);
    cudaGetSymbolAddress((void**)&pnf,   g_pn_f);
    cudaGetSymbolAddress((void**)&p2part, g_p2part);
    cudaGetSymbolAddress((void**)&qppart, g_qppart);
    cudaGetSymbolAddress((void**)&ssqpart, g_ssqpart);
    cudaGetSymbolAddress((void**)&invn,  g_invn);
    cudaGetSymbolAddress((void**)&tw,    g_tw);

    constexpr int SMEM_SZ = 3 * 2 * 128 * 64 * 2;   // 98304
    constexpr int SIM_SMEM = 2 * (128 * 64 * 2 + 64 * 64 * 2);  // 49152
    cudaFuncSetAttribute(mma_gemm<56>, cudaFuncAttributeMaxDynamicSharedMemorySize, SMEM_SZ);
    cudaFuncSetAttribute(mma_gemm<7>,  cudaFuncAttributeMaxDynamicSharedMemorySize, SMEM_SZ);
    cudaFuncSetAttribute(sim_attn_kernel, cudaFuncAttributeMaxDynamicSharedMemorySize, SIM_SMEM);

    const int B = B_ROWS;
    size_t n4;

    // 0-2: fp16 conversions (deps of the big GEMM)
    n4 = (size_t)B * D_DIM / 4;
    tohalf_kernel<<<(unsigned)((n4 + 255) / 256), 256>>>(x, xh, n4);
    n4 = (size_t)D_DIM * D_DIM / 4;
    tohalf_kernel<<<(unsigned)((n4 + 255) / 256), 256>>>(W_in, winh, n4);
    n4 = (size_t)D_HALF * D_DIM / 4;
    tohalf_kernel<<<(unsigned)((n4 + 255) / 256), 256>>>(Wr1, wr1h, n4);

    // 3: G1+G2 fused (G1 -> row ssq partials; G2 -> r fp16)  [ncu capture slot]
    mma_gemm<56><<<dim3(D_DIM / 128 + D_HALF / 128, B / 128), 256, SMEM_SZ>>>(
        xh, nullptr, winh, b_in, nullptr, nullptr,
        D_DIM, D_DIM, 0, D_DIM, 0,
        wr1h, br1, rh, D_HALF, D_DIM / 128, ssqpart);

    // 4: prototype normalization (fp32) + static salience terms
    proto_prep<<<S_PROTO, 256>>>(protos, conf, age, ev, pnf);

    // 5: pack W_out1 into wcomb
    wout1_pack_kernel<<<(D_DIM * D_DIM / 4) / 256, 256>>>(W_out, wcomb);

    // 6-7: q = pn @ W_in (fp16)
    qp_kernel<<<dim3(D_DIM / 128, 8), 256>>>(pnf, W_in, qppart);
    qp_reduce_kernel<<<(S_PROTO * D_DIM) / 256, 256>>>(qppart, qph);

    // 8: invn from ssq partials
    ssq_combine_kernel<<<B / 256, 256>>>(ssqpart, invn);

    // 9: type weights
    type_weights_kernel<<<B / 8, 256>>>(rh, Wr2, br2, tw);

    // 10: fused sim + salience + softmax -> attn (fp16)
    sim_attn_kernel<<<B / 128, 256, SIM_SMEM>>>(xh, qph, tw, invn, attnh);

    // 11-12: P2 into wcomb
    p2_kernel<<<dim3(D_DIM / 128, 4), 256>>>(protos, W_out, p2part);
    p2_reduce_kernel<<<(S_PROTO * D_DIM) / 256, 256>>>(p2part, wcomb);

    // 13: G3: out = gelu([x | attn] @ [W_out1 | P2]^T + b_out) + x
    mma_gemm<7><<<dim3(D_DIM / 128, B / 128), 256, SMEM_SZ>>>(
        xh, attnh, wcomb, b_out, x, out,
        D_DIM, KCOMB, D_DIM, D_DIM, S_PROTO,
        nullptr, nullptr, nullptr, 0, 0x7FFFFFFF, nullptr);

    // 14: final LayerNorm
    layernorm_inplace<<<B, 256>>>(out, ln_w, ln_b);
}

// round 11
// speedup vs baseline: 1.0337x; 1.0337x over previous
#include <cuda_runtime.h>
#include <cuda_fp16.h>
#include <math.h>
#include <stdint.h>

#define B_ROWS 16384
#define D_DIM  2048
#define D_HALF 1024
#define S_PROTO 64
#define KCOMB  (D_DIM + S_PROTO)   // 2112

// ---------------------------------------------------------------------------
// Scratch (device globals; allocation-free per harness rules)
// ---------------------------------------------------------------------------
__device__ __half g_x_h[(size_t)B_ROWS * D_DIM];
__device__ __half g_Win_h[(size_t)D_DIM * D_DIM];
__device__ __half g_Wr1_h[(size_t)D_HALF * D_DIM];
__device__ __half g_wcomb[(size_t)D_DIM * KCOMB];      // [W_out1 | P2^T] fp16
__device__ __half g_attn_h[(size_t)B_ROWS * S_PROTO];
__device__ __half g_r_h[(size_t)B_ROWS * D_HALF];      // r in fp16
__device__ __half g_qp_h[(size_t)S_PROTO * D_DIM];     // q = pn @ W_in, fp16
__device__ float g_pn_f[(size_t)S_PROTO * D_DIM];      // normalized protos fp32
__device__ float g_p2part[4 * S_PROTO * D_DIM];
__device__ float g_qppart[8 * S_PROTO * D_DIM];
__device__ float g_ssqpart[16 * B_ROWS];               // per n-tile row ssq
__device__ float g_tw[(size_t)B_ROWS * 4];
__device__ float g_base[S_PROTO];
__device__ float g_wsimc[S_PROTO];

// ---------------------------------------------------------------------------
// PTX helpers (baseline ISA: mma.sync / ldmatrix / cp.async)
// ---------------------------------------------------------------------------
__device__ __forceinline__ uint32_t smem_to_u32(const void* p) {
    uint32_t a;
    asm("{ .reg .u64 t; cvta.to.shared.u64 t, %1; cvt.u32.u64 %0, t; }"
        : "=r"(a) : "l"(p));
    return a;
}

__device__ __forceinline__ void cpasync16(uint32_t saddr, const void* g) {
    asm volatile("cp.async.cg.shared.global [%0], [%1], 16;"
                 :: "r"(saddr), "l"(g));
}
#define CP_COMMIT() asm volatile("cp.async.commit_group;" ::: "memory")
#define CP_WAIT(n)  asm volatile("cp.async.wait_group %0;" :: "n"(n) : "memory")

__device__ __forceinline__ void ldsm4(uint32_t* r, uint32_t addr) {
    asm volatile("ldmatrix.sync.aligned.m8n8.x4.shared.b16 {%0,%1,%2,%3}, [%4];"
                 : "=r"(r[0]), "=r"(r[1]), "=r"(r[2]), "=r"(r[3]) : "r"(addr));
}

__device__ __forceinline__ void mma_f16(float* d, const uint32_t* a, const uint32_t* b) {
    asm volatile(
        "mma.sync.aligned.m16n8k16.row.col.f32.f16.f16.f32 "
        "{%0,%1,%2,%3}, {%4,%5,%6,%7}, {%8,%9}, {%0,%1,%2,%3};"
        : "+f"(d[0]), "+f"(d[1]), "+f"(d[2]), "+f"(d[3])
        : "r"(a[0]), "r"(a[1]), "r"(a[2]), "r"(a[3]), "r"(b[0]), "r"(b[1]));
}

// ---------------------------------------------------------------------------
// Misc helpers
// ---------------------------------------------------------------------------
__device__ __forceinline__ float gelu_exact(float v) {
    return 0.5f * v * (1.0f + erff(v * 0.70710678118654752440f));
}

__device__ __forceinline__ float block_reduce_sum(float v) {
    __shared__ float sh[32];
    int lane = threadIdx.x & 31, w = threadIdx.x >> 5;
    #pragma unroll
    for (int o = 16; o; o >>= 1) v += __shfl_xor_sync(0xFFFFFFFFu, v, o);
    if (lane == 0) sh[w] = v;
    __syncthreads();
    float r = (threadIdx.x < (blockDim.x >> 5)) ? sh[threadIdx.x] : 0.0f;
    if (w == 0) {
        #pragma unroll
        for (int o = 16; o; o >>= 1) r += __shfl_xor_sync(0xFFFFFFFFu, r, o);
        if (lane == 0) sh[0] = r;
    }
    __syncthreads();
    float out = sh[0];
    __syncthreads();
    return out;
}

// ---------------------------------------------------------------------------
// fp32 -> fp16 convert (vectorized, contiguous)
// ---------------------------------------------------------------------------
__global__ void tohalf_kernel(const float* __restrict__ s,
                              __half* __restrict__ d, size_t n4)
{
    size_t i = (size_t)blockIdx.x * blockDim.x + threadIdx.x;
    if (i >= n4) return;
    float4 v = reinterpret_cast<const float4*>(s)[i];
    __half2 h0 = __floats2half2_rn(v.x, v.y);
    __half2 h1 = __floats2half2_rn(v.z, v.w);
    uint2 o;
    o.x = *reinterpret_cast<uint32_t*>(&h0);
    o.y = *reinterpret_cast<uint32_t*>(&h1);
    reinterpret_cast<uint2*>(d)[i] = o;
}

// ---------------------------------------------------------------------------
// Pack W_out[:, 0:2048] (stride 4096) into wcomb[:, 0:2048] (stride 2112) fp16
// ---------------------------------------------------------------------------
__global__ void wout1_pack_kernel(const float* __restrict__ wout,
                                  __half* __restrict__ wcomb)
{
    int idx = blockIdx.x * 256 + threadIdx.x;
    int row = idx >> 9;
    int c4  = idx & 511;
    float4 v = *reinterpret_cast<const float4*>(wout + (size_t)row * 2 * D_DIM + c4 * 4);
    __half2 h0 = __floats2half2_rn(v.x, v.y);
    __half2 h1 = __floats2half2_rn(v.z, v.w);
    uint2 o;
    o.x = *reinterpret_cast<uint32_t*>(&h0);
    o.y = *reinterpret_cast<uint32_t*>(&h1);
    *reinterpret_cast<uint2*>(wcomb + (size_t)row * KCOMB + c4 * 4) = o;
}

// ---------------------------------------------------------------------------
// P2 partials (k-split, conflict-free transposed tiles):
//   part[ks][s][n] = sum_{k in slice} protos[s][k] * W_out[n][2048+k]
// grid = (16, 4), 256 threads.
// ---------------------------------------------------------------------------
__global__ void __launch_bounds__(256)
p2_kernel(const float* __restrict__ protos, const float* __restrict__ wout,
          float* __restrict__ part)
{
    constexpr int BKC = 32;
    __shared__ float Pt[BKC][68];
    __shared__ float Wt[BKC][132];

    const int tid = threadIdx.x;
    const int n0 = blockIdx.x * 128;
    const int kb = blockIdx.y * 512;
    const int tr = tid >> 4;
    const int tc = tid & 15;

    float acc[4][8];
    #pragma unroll
    for (int i = 0; i < 4; i++)
        #pragma unroll
        for (int j = 0; j < 8; j++) acc[i][j] = 0.0f;

    for (int kt = 0; kt < 512; kt += BKC) {
        #pragma unroll
        for (int i = 0; i < 2; i++) {
            int idx = tid + i * 256;
            int s = idx >> 3, kq = (idx & 7) * 4;
            float4 v = *reinterpret_cast<const float4*>(
                protos + (size_t)s * D_DIM + kb + kt + kq);
            Pt[kq+0][s] = v.x; Pt[kq+1][s] = v.y;
            Pt[kq+2][s] = v.z; Pt[kq+3][s] = v.w;
        }
        #pragma unroll
        for (int i = 0; i < 4; i++) {
            int idx = tid + i * 256;
            int n = idx >> 3, kq = (idx & 7) * 4;
            float4 v = *reinterpret_cast<const float4*>(
                wout + (size_t)(n0 + n) * 2 * D_DIM + D_DIM + kb + kt + kq);
            Wt[kq+0][n] = v.x; Wt[kq+1][n] = v.y;
            Wt[kq+2][n] = v.z; Wt[kq+3][n] = v.w;
        }
        __syncthreads();
        #pragma unroll 8
        for (int k = 0; k < BKC; k++) {
            float4 p  = *reinterpret_cast<const float4*>(&Pt[k][tr * 4]);
            float4 wa = *reinterpret_cast<const float4*>(&Wt[k][tc * 8]);
            float4 wb = *reinterpret_cast<const float4*>(&Wt[k][tc * 8 + 4]);
            float pv[4] = {p.x, p.y, p.z, p.w};
            float wv[8] = {wa.x, wa.y, wa.z, wa.w, wb.x, wb.y, wb.z, wb.w};
            #pragma unroll
            for (int i = 0; i < 4; i++)
                #pragma unroll
                for (int j = 0; j < 8; j++)
                    acc[i][j] = fmaf(pv[i], wv[j], acc[i][j]);
        }
        __syncthreads();
    }

    float* dst = part + (size_t)blockIdx.y * S_PROTO * D_DIM;
    #pragma unroll
    for (int i = 0; i < 4; i++)
        #pragma unroll
        for (int j = 0; j < 8; j++)
            dst[(size_t)(tr * 4 + i) * D_DIM + n0 + tc * 8 + j] = acc[i][j];
}

// ---------------------------------------------------------------------------
// qp partials: part[ks][s][d] = sum_{j in slice} pn[s][j] * Win[j][d]
// grid = (16 d-tiles, 8 j-slices of 256), 256 threads.
// ---------------------------------------------------------------------------
__global__ void __launch_bounds__(256)
qp_kernel(const float* __restrict__ pnf, const float* __restrict__ win,
          float* __restrict__ part)
{
    constexpr int BKC = 32;
    __shared__ float Pt[BKC][68];
    __shared__ float Wt[BKC][132];

    const int tid = threadIdx.x;
    const int n0 = blockIdx.x * 128;         // d tile
    const int kb = blockIdx.y * 256;         // j slice
    const int tr = tid >> 4;
    const int tc = tid & 15;

    float acc[4][8];
    #pragma unroll
    for (int i = 0; i < 4; i++)
        #pragma unroll
        for (int j = 0; j < 8; j++) acc[i][j] = 0.0f;

    for (int kt = 0; kt < 256; kt += BKC) {
        #pragma unroll
        for (int i = 0; i < 2; i++) {
            int idx = tid + i * 256;
            int s = idx >> 3, jq = (idx & 7) * 4;
            float4 v = *reinterpret_cast<const float4*>(
                pnf + (size_t)s * D_DIM + kb + kt + jq);
            Pt[jq+0][s] = v.x; Pt[jq+1][s] = v.y;
            Pt[jq+2][s] = v.z; Pt[jq+3][s] = v.w;
        }
        #pragma unroll
        for (int i = 0; i < 4; i++) {
            int idx = tid + i * 256;
            int j = idx >> 5, d4 = idx & 31;
            float4 v = *reinterpret_cast<const float4*>(
                win + (size_t)(kb + kt + j) * D_DIM + n0 + d4 * 4);
            Wt[j][d4*4+0] = v.x; Wt[j][d4*4+1] = v.y;
            Wt[j][d4*4+2] = v.z; Wt[j][d4*4+3] = v.w;
        }
        __syncthreads();
        #pragma unroll 8
        for (int k = 0; k < BKC; k++) {
            float4 p  = *reinterpret_cast<const float4*>(&Pt[k][tr * 4]);
            float4 wa = *reinterpret_cast<const float4*>(&Wt[k][tc * 8]);
            float4 wb = *reinterpret_cast<const float4*>(&Wt[k][tc * 8 + 4]);
            float pv[4] = {p.x, p.y, p.z, p.w};
            float wv[8] = {wa.x, wa.y, wa.z, wa.w, wb.x, wb.y, wb.z, wb.w};
            #pragma unroll
            for (int i = 0; i < 4; i++)
                #pragma unroll
                for (int j = 0; j < 8; j++)
                    acc[i][j] = fmaf(pv[i], wv[j], acc[i][j]);
        }
        __syncthreads();
    }

    float* dst = part + (size_t)blockIdx.y * S_PROTO * D_DIM;
    #pragma unroll
    for (int i = 0; i < 4; i++)
        #pragma unroll
        for (int j = 0; j < 8; j++)
            dst[(size_t)(tr * 4 + i) * D_DIM + n0 + tc * 8 + j] = acc[i][j];
}

// ---------------------------------------------------------------------------
// Combined reduce: blocks [0,512) -> qp (8-way, fixed order) -> qph;
//                  blocks [512,1024) -> p2 (4-way, fixed order) -> wcomb tail.
// ---------------------------------------------------------------------------
__global__ void prep_reduce_kernel(const float* __restrict__ qppart,
                                   const float* __restrict__ p2part,
                                   __half* __restrict__ qph,
                                   __half* __restrict__ wcomb)
{
    int b = blockIdx.x;
    if (b < 512) {
        int idx = b * 256 + threadIdx.x;        // over 64*2048
        float v = 0.0f;
        #pragma unroll
        for (int t = 0; t < 8; t++) v += qppart[(size_t)t * S_PROTO * D_DIM + idx];
        qph[idx] = __float2half_rn(v);
    } else {
        int idx = (b - 512) * 256 + threadIdx.x;
        int s = idx >> 11;
        int n = idx & 2047;
        size_t o = (size_t)s * D_DIM + n;
        float v = p2part[o] + p2part[o + S_PROTO * D_DIM]
                + p2part[o + 2 * S_PROTO * D_DIM] + p2part[o + 3 * S_PROTO * D_DIM];
        wcomb[(size_t)n * KCOMB + D_DIM + s] = __float2half_rn(v);
    }
}

// ---------------------------------------------------------------------------
// Single-pass fp16 HMMA GEMM.
// MODE bits: 1=gelu, 2=+Xres(fp32), 4=split-A, 8=dual-output (second gelued),
//            16=fp16 outputs, 32=first-output is row-ssq (no C write).
// BM=BN=128, BK=64, 3-stage cp.async, 256 threads, 2 CTAs/SM.
// Incremental per-thread global pointers; hoisted LDSM swizzle bases.
// ---------------------------------------------------------------------------
template<int MODE>
__global__ void __launch_bounds__(256, 2)
mma_gemm(const __half* __restrict__ A, const __half* __restrict__ A2,
         const __half* __restrict__ Bm,
         const float* __restrict__ bias, const float* __restrict__ Xres,
         void* __restrict__ C, int N, int K, int Ksplit,
         int strideA, int strideA2,
         const __half* __restrict__ B2,
         const float* __restrict__ bias2, void* __restrict__ C2,
         int N2, int NXtiles, float* __restrict__ ssqpart)
{
    constexpr int BM = 128, BK = 64, STAGES = 3;
    constexpr int TILE_B  = BM * BK * 2;
    constexpr int STAGE_B = 2 * TILE_B;

    extern __shared__ __align__(16) char smem[];
    const uint32_t sbase = smem_to_u32(smem);

    const int tid  = threadIdx.x;
    const int wid  = tid >> 5, lane = tid & 31;
    const int m0 = blockIdx.y * BM;

    int bx = blockIdx.x;
    bool second = false;
    if constexpr (MODE & 8) {
        if (bx >= NXtiles) { second = true; bx -= NXtiles; }
    }
    const __half* pB = second ? B2 : Bm;
    const float* pbias = second ? bias2 : bias;
    void* pC = second ? C2 : C;
    const int NN = second ? N2 : N;
    const int n0 = bx * BM;
    const bool do_gelu = (MODE & 1) || second;

    const int wm = (wid >> 2) * 64;
    const int wn = (wid & 3) * 32;

    float acc[4][4][4];
    #pragma unroll
    for (int i = 0; i < 4; i++)
        #pragma unroll
        for (int j = 0; j < 4; j++)
            #pragma unroll
            for (int k = 0; k < 4; k++) acc[i][j][k] = 0.0f;

    const int nk = K / BK;

    // --- incremental per-thread load pointers (chunk stride 32 rows) ---
    const int rowb = tid >> 3;                 // 0..31 (chunk i adds 32*i)
    const int gld  = tid & 7;
    const uint32_t sw_base = rowb * 128 + ((gld ^ (rowb & 7)) * 16);
    const __half* pAp = A + (size_t)(m0 + rowb) * strideA + gld * 8;
    const __half* pBp = pB + (size_t)(n0 + rowb) * K + gld * 8;
    int sAcur = strideA;
    const int kswitch = (MODE & 4) ? (Ksplit / BK) : 0x7FFFFFFF;

    auto load_stage = [&](int s, int t) {
        if constexpr (MODE & 4) {
            if (t == kswitch) {
                pAp = A2 + (size_t)(m0 + rowb) * strideA2 + gld * 8;
                sAcur = strideA2;
            }
        }
        const uint32_t sb = sbase + s * STAGE_B;
        #pragma unroll
        for (int i = 0; i < 4; i++) {
            uint32_t so = sb + sw_base + i * (32 * 128);
            cpasync16(so, pAp + (size_t)i * 32 * sAcur);
            cpasync16(so + TILE_B, pBp + (size_t)i * 32 * K);
        }
        pAp += BK; pBp += BK;
    };

    // --- hoisted LDSM swizzle bases (row&7 == lane&7 for all fragments) ---
    const uint32_t r7 = (uint32_t)(lane & 7);
    const uint32_t gaH = (uint32_t)(lane >> 4);         // A: k-half select
    const uint32_t gbH = (uint32_t)((lane >> 3) & 1);   // B: k-half select
    uint32_t abase[4], bbase[2];
    #pragma unroll
    for (int mf = 0; mf < 4; mf++)
        abase[mf] = (uint32_t)(wm + mf * 16 + (lane & 15)) * 128;
    #pragma unroll
    for (int nf2 = 0; nf2 < 2; nf2++)
        bbase[nf2] = TILE_B +
            (uint32_t)(wn + nf2 * 16 + ((lane >> 4) & 1) * 8 + (lane & 7)) * 128;

    auto compute_stage = [&](int s) {
        const uint32_t sb = sbase + s * STAGE_B;
        #pragma unroll
        for (int ks = 0; ks < 4; ks++) {
            const uint32_t gA = ((ks * 2 + gaH) ^ r7) << 4;
            const uint32_t gB = ((ks * 2 + gbH) ^ r7) << 4;
            uint32_t afr[4][4], bfr[2][4];
            #pragma unroll
            for (int mf = 0; mf < 4; mf++)
                ldsm4(afr[mf], sb + abase[mf] + gA);
            #pragma unroll
            for (int nf2 = 0; nf2 < 2; nf2++)
                ldsm4(bfr[nf2], sb + bbase[nf2] + gB);
            #pragma unroll
            for (int mf = 0; mf < 4; mf++)
                #pragma unroll
                for (int nf = 0; nf < 4; nf++)
                    mma_f16(acc[mf][nf], afr[mf], &bfr[nf >> 1][(nf & 1) * 2]);
        }
    };

    load_stage(0, 0); CP_COMMIT();
    load_stage(1, 1); CP_COMMIT();

    for (int t = 0; t < nk; t++) {
        CP_WAIT(STAGES - 2);
        __syncthreads();
        if (t + STAGES - 1 < nk) load_stage((t + STAGES - 1) % STAGES, t + STAGES - 1);
        CP_COMMIT();
        compute_stage(t % STAGES);
    }

    bool ssq_mode = false;
    if constexpr (MODE & 32) ssq_mode = !second;

    if (ssq_mode) {
        float rs[4][2];
        #pragma unroll
        for (int mf = 0; mf < 4; mf++)
            #pragma unroll
            for (int half = 0; half < 2; half++) {
                float s = 0.0f;
                #pragma unroll
                for (int nf = 0; nf < 4; nf++)
                    #pragma unroll
                    for (int k = 0; k < 2; k++) {
                        int col = n0 + wn + nf * 8 + (lane & 3) * 2 + k;
                        float v = acc[mf][nf][half * 2 + k] + pbias[col];
                        s = fmaf(v, v, s);
                    }
                rs[mf][half] = s;
            }
        #pragma unroll
        for (int mf = 0; mf < 4; mf++)
            #pragma unroll
            for (int half = 0; half < 2; half++) {
                rs[mf][half] += __shfl_xor_sync(0xFFFFFFFFu, rs[mf][half], 1);
                rs[mf][half] += __shfl_xor_sync(0xFFFFFFFFu, rs[mf][half], 2);
            }
        __syncthreads();
        float* ssqsm = reinterpret_cast<float*>(smem);
        if ((lane & 3) == 0) {
            #pragma unroll
            for (int mf = 0; mf < 4; mf++)
                #pragma unroll
                for (int half = 0; half < 2; half++)
                    ssqsm[wid * 64 + mf * 16 + (lane >> 2) + half * 8] = rs[mf][half];
        }
        __syncthreads();
        if (tid < 128) {
            int group = tid >> 6, r = tid & 63;
            float v = ssqsm[(group * 4 + 0) * 64 + r]
                    + ssqsm[(group * 4 + 1) * 64 + r]
                    + ssqsm[(group * 4 + 2) * 64 + r]
                    + ssqsm[(group * 4 + 3) * 64 + r];
            ssqpart[(size_t)bx * B_ROWS + m0 + group * 64 + r] = v;
        }
    } else {
        #pragma unroll
        for (int mf = 0; mf < 4; mf++)
            #pragma unroll
            for (int nf = 0; nf < 4; nf++)
                #pragma unroll
                for (int half = 0; half < 2; half++) {
                    int row = m0 + wm + mf * 16 + (lane >> 2) + half * 8;
                    int col = n0 + wn + nf * 8 + (lane & 3) * 2;
                    float v0 = acc[mf][nf][half * 2 + 0] + pbias[col];
                    float v1 = acc[mf][nf][half * 2 + 1] + pbias[col + 1];
                    if (do_gelu) { v0 = gelu_exact(v0); v1 = gelu_exact(v1); }
                    if constexpr (MODE & 2) {
                        float2 xr = *reinterpret_cast<const float2*>(
                            &Xres[(size_t)row * NN + col]);
                        v0 += xr.x; v1 += xr.y;
                    }
                    if constexpr (MODE & 16) {
                        __half2 o = __floats2half2_rn(v0, v1);
                        *reinterpret_cast<__half2*>(
                            (__half*)pC + (size_t)row * NN + col) = o;
                    } else {
                        float2 o; o.x = v0; o.y = v1;
                        *reinterpret_cast<float2*>(
                            (float*)pC + (size_t)row * NN + col) = o;
                    }
                }
    }
}

// ---------------------------------------------------------------------------
// sim_attn v4: fused invn (from ssq partials) + HMMA sim (fp16 x @ fp16 qp^T)
// + salience + softmax -> attn fp16. 128 rows/block, 256 threads.
// ---------------------------------------------------------------------------
__global__ void __launch_bounds__(256)
sim_attn_kernel(const __half* __restrict__ X, const __half* __restrict__ QP,
                const float* __restrict__ tw, const float* __restrict__ ssqpart,
                __half* __restrict__ attn)
{
    constexpr int BK = 64;
    constexpr int H_B  = 128 * BK * 2;
    constexpr int PN_B = S_PROTO * BK * 2;
    constexpr int STAGE_B = H_B + PN_B;
    constexpr int INVN_OFF = 2 * STAGE_B;   // 49152

    extern __shared__ __align__(16) char dsm[];
    const uint32_t sbase = smem_to_u32(dsm);
    float* sal = reinterpret_cast<float*>(dsm);
    float* invn_sm = reinterpret_cast<float*>(dsm + INVN_OFF);

    const int tid = threadIdx.x;
    const int wid = tid >> 5, lane = tid & 31;
    const int m0 = blockIdx.x * 128;
    const int K = D_DIM;

    // fused invn: same fixed summation order as the old ssq_combine kernel
    if (tid < 128) {
        float s = 0.0f;
        #pragma unroll
        for (int t = 0; t < 16; t++) s += ssqpart[(size_t)t * B_ROWS + m0 + tid];
        invn_sm[tid] = 1.0f / fmaxf(sqrtf(s), 1e-12f);
    }

    float acc[8][4];
    #pragma unroll
    for (int i = 0; i < 8; i++)
        #pragma unroll
        for (int j = 0; j < 4; j++) acc[i][j] = 0.0f;

    uint4 hReg[4]; uint4 pReg[2];

    auto fetch = [&](int t) {
        const int k0 = t * BK;
        #pragma unroll
        for (int i = 0; i < 4; i++) {
            int idx = tid + i * 256;
            int row = idx >> 3, g = idx & 7;
            hReg[i] = *reinterpret_cast<const uint4*>(
                X + (size_t)(m0 + row) * K + k0 + g * 8);
        }
        #pragma unroll
        for (int i = 0; i < 2; i++) {
            int idx = tid + i * 256;
            int s = idx >> 3, g = idx & 7;
            pReg[i] = *reinterpret_cast<const uint4*>(
                QP + (size_t)s * K + k0 + g * 8);
        }
    };
    auto stash = [&](int buf) {
        char* cb = dsm + buf * STAGE_B;
        #pragma unroll
        for (int i = 0; i < 4; i++) {
            int idx = tid + i * 256;
            int row = idx >> 3, g = idx & 7;
            *reinterpret_cast<uint4*>(cb + row * 128 + ((g ^ (row & 7)) * 16)) = hReg[i];
        }
        #pragma unroll
        for (int i = 0; i < 2; i++) {
            int idx = tid + i * 256;
            int s = idx >> 3, g = idx & 7;
            *reinterpret_cast<uint4*>(cb + H_B + s * 128 + ((g ^ (s & 7)) * 16)) = pReg[i];
        }
    };
    auto compute = [&](int buf) {
        const uint32_t sb = sbase + buf * STAGE_B;
        #pragma unroll
        for (int ks = 0; ks < 4; ks++) {
            uint32_t afr[4], bfr[4][4];
            {
                int row = wid * 16 + (lane & 15);
                int g   = ks * 2 + (lane >> 4);
                ldsm4(afr, sb + row * 128 + ((g ^ (row & 7)) * 16));
            }
            #pragma unroll
            for (int nf2 = 0; nf2 < 4; nf2++) {
                int nrow = nf2 * 16 + ((lane >> 4) & 1) * 8 + (lane & 7);
                int g    = ks * 2 + ((lane >> 3) & 1);
                ldsm4(bfr[nf2], sb + H_B + nrow * 128 + ((g ^ (nrow & 7)) * 16));
            }
            #pragma unroll
            for (int nf = 0; nf < 8; nf++)
                mma_f16(acc[nf], afr, &bfr[nf >> 1][(nf & 1) * 2]);
        }
    };

    const int nk = K / BK;
    fetch(0); stash(0);
    __syncthreads();
    for (int t = 0; t < nk; t++) {
        const int cur = t & 1;
        if (t + 1 < nk) fetch(t + 1);
        compute(cur);
        if (t + 1 < nk) stash(cur ^ 1);
        __syncthreads();
    }

    // salience into smem (overlay over stage buffers; invn region untouched)
    {
        int r0 = wid * 16 + (lane >> 2);
        #pragma unroll
        for (int half = 0; half < 2; half++) {
            int row = r0 + half * 8;
            float invn = invn_sm[row];
            #pragma unroll
            for (int nf = 0; nf < 8; nf++) {
                int col = nf * 8 + (lane & 3) * 2;
                float twv = tw[(size_t)(m0 + row) * 4 + (col >> 4)];
                float v0 = g_wsimc[col] * twv * (acc[nf][half*2+0] * invn) + g_base[col];
                float twv1 = tw[(size_t)(m0 + row) * 4 + ((col + 1) >> 4)];
                float v1 = g_wsimc[col+1] * twv1 * (acc[nf][half*2+1] * invn) + g_base[col+1];
                sal[row * 65 + col]     = fminf(fmaxf(v0, 0.0f), 1.0f);
                sal[row * 65 + col + 1] = fminf(fmaxf(v1, 0.0f), 1.0f);
            }
        }
    }
    __syncthreads();

    // softmax over 64 per row; 2 threads per row
    {
        int row = tid >> 1, half = tid & 1;
        const float* srow = &sal[row * 65 + half * 32];
        float m = -1e30f;
        #pragma unroll
        for (int c = 0; c < 32; c++) m = fmaxf(m, srow[c]);
        m = fmaxf(m, __shfl_xor_sync(0xFFFFFFFFu, m, 1));
        const float invT = 1.0f / 0.07f;
        float e[32], s = 0.0f;
        #pragma unroll
        for (int c = 0; c < 32; c++) { e[c] = expf((srow[c] - m) * invT); s += e[c]; }
        s += __shfl_xor_sync(0xFFFFFFFFu, s, 1);
        float inv = 1.0f / s;
        __half* dst = &attn[(size_t)(m0 + row) * S_PROTO + half * 32];
        #pragma unroll
        for (int c = 0; c < 32; c += 2) {
            __half2 o = __floats2half2_rn(e[c] * inv, e[c+1] * inv);
            *reinterpret_cast<__half2*>(dst + c) = o;
        }
    }
}

// ---------------------------------------------------------------------------
// Prototype prep: normalized protos -> fp32, plus static salience terms
// ---------------------------------------------------------------------------
__global__ void proto_prep(const float* __restrict__ protos,
                           const float* __restrict__ conf,
                           const float* __restrict__ age,
                           const float* __restrict__ ev,
                           float* __restrict__ pn_f)
{
    const int s = blockIdx.x;
    float ss = 0.0f;
    for (int k = threadIdx.x; k < D_DIM; k += 256) {
        float v = protos[(size_t)s * D_DIM + k];
        ss += v * v;
    }
    float tot = block_reduce_sum(ss);
    float scale = 1.0f / fmaxf(sqrtf(tot), 1e-12f);
    for (int k = threadIdx.x; k < D_DIM; k += 256)
        pn_f[(size_t)s * D_DIM + k] = protos[(size_t)s * D_DIM + k] * scale;

    if (threadIdx.x == 0) {
        float evmax = 0.0f;
        for (int i = 0; i < S_PROTO; i++) evmax = fmaxf(evmax, ev[i]);
        float freq = logf(ev[s] + 1.0f) / (logf(evmax + 2.0f) + 1e-8f);
        float rec  = expf(-age[s] * (1.0f / 200.0f));
        g_base[s]  = 0.2f * rec + 0.15f * freq + 0.1f * conf[s] + 0.1f * 0.9f;
        g_wsimc[s] = 0.45f * conf[s];
    }
}

// ---------------------------------------------------------------------------
// Type weights softmax (4 logits), r in fp16. 1 warp per row.
// ---------------------------------------------------------------------------
__global__ void type_weights_kernel(const __half* __restrict__ r,
                                    const float* __restrict__ Wr2,
                                    const float* __restrict__ br2,
                                    float* __restrict__ tw)
{
    const int warp = threadIdx.x >> 5, lane = threadIdx.x & 31;
    const int b = blockIdx.x * 8 + warp;
    const uint4* rp = reinterpret_cast<const uint4*>(r + (size_t)b * D_HALF);
    float acc[4] = {0.f, 0.f, 0.f, 0.f};
    for (int i = lane; i < D_HALF / 8; i += 32) {
        uint4 rv = rp[i];
        float rf[8];
        #pragma unroll
        for (int q = 0; q < 4; q++) {
            __half2 hv = *reinterpret_cast<__half2*>(
                reinterpret_cast<uint32_t*>(&rv) + q);
            float2 f = __half22float2(hv);
            rf[q*2] = f.x; rf[q*2+1] = f.y;
        }
        #pragma unroll
        for (int t = 0; t < 4; t++) {
            const float* wr = Wr2 + (size_t)t * D_HALF + i * 8;
            float4 w0 = *reinterpret_cast<const float4*>(wr);
            float4 w1 = *reinterpret_cast<const float4*>(wr + 4);
            acc[t] += rf[0]*w0.x + rf[1]*w0.y + rf[2]*w0.z + rf[3]*w0.w
                    + rf[4]*w1.x + rf[5]*w1.y + rf[6]*w1.z + rf[7]*w1.w;
        }
    }
    #pragma unroll
    for (int t = 0; t < 4; t++)
        #pragma unroll
        for (int o = 16; o; o >>= 1)
            acc[t] += __shfl_xor_sync(0xFFFFFFFFu, acc[t], o);
    if (lane == 0) {
        float z[4], m = -1e30f;
        #pragma unroll
        for (int t = 0; t < 4; t++) { z[t] = acc[t] + br2[t]; m = fmaxf(m, z[t]); }
        float s = 0.0f;
        #pragma unroll
        for (int t = 0; t < 4; t++) { z[t] = expf(z[t] - m); s += z[t]; }
        float inv = 1.0f / s;
        #pragma unroll
        for (int t = 0; t < 4; t++) tw[(size_t)b * 4 + t] = z[t] * inv;
    }
}

// ---------------------------------------------------------------------------
// In-place LayerNorm over D
// ---------------------------------------------------------------------------
__global__ void layernorm_inplace(float* __restrict__ y,
                                  const float* __restrict__ w,
                                  const float* __restrict__ bb)
{
    const size_t base = (size_t)blockIdx.x * D_DIM;
    float4* yp = reinterpret_cast<float4*>(y + base);
    float4 v[2];
    float sum = 0.0f;
    #pragma unroll
    for (int i = 0; i < 2; i++) {
        v[i] = yp[threadIdx.x + 256 * i];
        sum += v[i].x + v[i].y + v[i].z + v[i].w;
    }
    float mu = block_reduce_sum(sum) * (1.0f / D_DIM);
    float sq = 0.0f;
    #pragma unroll
    for (int i = 0; i < 2; i++) {
        float dx = v[i].x - mu, dy = v[i].y - mu, dz = v[i].z - mu, dw = v[i].w - mu;
        sq += dx*dx + dy*dy + dz*dz + dw*dw;
    }
    float var = block_reduce_sum(sq) * (1.0f / D_DIM);
    float rstd = rsqrtf(var + 1e-5f);
    #pragma unroll
    for (int i = 0; i < 2; i++) {
        int col = (threadIdx.x + 256 * i) * 4;
        float4 wv = *reinterpret_cast<const float4*>(&w[col]);
        float4 bv = *reinterpret_cast<const float4*>(&bb[col]);
        float4 o;
        o.x = wv.x * (v[i].x - mu) * rstd + bv.x;
        o.y = wv.y * (v[i].y - mu) * rstd + bv.y;
        o.z = wv.z * (v[i].z - mu) * rstd + bv.z;
        o.w = wv.w * (v[i].w - mu) * rstd + bv.w;
        yp[threadIdx.x + 256 * i] = o;
    }
}

// ---------------------------------------------------------------------------
// Launch
// ---------------------------------------------------------------------------
extern "C" void kernel_launch(void* const* d_in, const int* in_sizes, int n_in,
                              void* d_out, int out_size)
{
    const float* x      = (const float*)d_in[0];
    const float* protos = (const float*)d_in[1];
    const float* conf   = (const float*)d_in[2];
    const float* age    = (const float*)d_in[3];
    const float* ev     = (const float*)d_in[4];
    const float* W_in   = (const float*)d_in[5];
    const float* b_in   = (const float*)d_in[6];
    const float* Wr1    = (const float*)d_in[7];
    const float* br1    = (const float*)d_in[8];
    const float* Wr2    = (const float*)d_in[9];
    const float* br2    = (const float*)d_in[10];
    const float* W_out  = (const float*)d_in[11];
    const float* b_out  = (const float*)d_in[12];
    const float* ln_w   = (const float*)d_in[13];
    const float* ln_b   = (const float*)d_in[14];
    float* out = (float*)d_out;

    __half *xh, *winh, *wr1h, *wcomb, *attnh, *rh, *qph;
    float *tw, *p2part, *qppart, *pnf, *ssqpart;
    cudaGetSymbolAddress((void**)&xh,    g_x_h);
    cudaGetSymbolAddress((void**)&winh,  g_Win_h);
    cudaGetSymbolAddress((void**)&wr1h,  g_Wr1_h);
    cudaGetSymbolAddress((void**)&wcomb, g_wcomb);
    cudaGetSymbolAddress((void**)&attnh, g_attn_h);
    cudaGetSymbolAddress((void**)&rh,    g_r_h);
    cudaGetSymbolAddress((void**)&qph,   g_qp_h);
    cudaGetSymbolAddress((void**)&pnf,   g_pn_f);
    cudaGetSymbolAddress((void**)&p2part, g_p2part);
    cudaGetSymbolAddress((void**)&qppart, g_qppart);
    cudaGetSymbolAddress((void**)&ssqpart, g_ssqpart);
    cudaGetSymbolAddress((void**)&tw,    g_tw);

    constexpr int SMEM_SZ = 3 * 2 * 128 * 64 * 2;   // 98304
    constexpr int SIM_SMEM = 2 * (128 * 64 * 2 + 64 * 64 * 2) + 512;  // 49664
    cudaFuncSetAttribute(mma_gemm<56>, cudaFuncAttributeMaxDynamicSharedMemorySize, SMEM_SZ);
    cudaFuncSetAttribute(mma_gemm<7>,  cudaFuncAttributeMaxDynamicSharedMemorySize, SMEM_SZ);
    cudaFuncSetAttribute(sim_attn_kernel, cudaFuncAttributeMaxDynamicSharedMemorySize, SIM_SMEM);

    const int B = B_ROWS;
    size_t n4;

    // 0-2: fp16 conversions (deps of the big GEMM)
    n4 = (size_t)B * D_DIM / 4;
    tohalf_kernel<<<(unsigned)((n4 + 255) / 256), 256>>>(x, xh, n4);
    n4 = (size_t)D_DIM * D_DIM / 4;
    tohalf_kernel<<<(unsigned)((n4 + 255) / 256), 256>>>(W_in, winh, n4);
    n4 = (size_t)D_HALF * D_DIM / 4;
    tohalf_kernel<<<(unsigned)((n4 + 255) / 256), 256>>>(Wr1, wr1h, n4);

    // 3: G1+G2 fused (G1 -> row ssq partials; G2 -> r fp16)  [ncu capture slot]
    mma_gemm<56><<<dim3(D_DIM / 128 + D_HALF / 128, B / 128), 256, SMEM_SZ>>>(
        xh, nullptr, winh, b_in, nullptr, nullptr,
        D_DIM, D_DIM, 0, D_DIM, 0,
        wr1h, br1, rh, D_HALF, D_DIM / 128, ssqpart);

    // 4: prototype normalization (fp32) + static salience terms
    proto_prep<<<S_PROTO, 256>>>(protos, conf, age, ev, pnf);

    // 5: pack W_out1 into wcomb
    wout1_pack_kernel<<<(D_DIM * D_DIM / 4) / 256, 256>>>(W_out, wcomb);

    // 6-7: q = pn @ W_in partials; P2 partials
    qp_kernel<<<dim3(D_DIM / 128, 8), 256>>>(pnf, W_in, qppart);
    p2_kernel<<<dim3(D_DIM / 128, 4), 256>>>(protos, W_out, p2part);

    // 8: combined reduce (qp -> qph, p2 -> wcomb tail)
    prep_reduce_kernel<<<1024, 256>>>(qppart, p2part, qph, wcomb);

    // 9: type weights
    type_weights_kernel<<<B / 8, 256>>>(rh, Wr2, br2, tw);

    // 10: fused invn + sim + salience + softmax -> attn (fp16)
    sim_attn_kernel<<<B / 128, 256, SIM_SMEM>>>(xh, qph, tw, ssqpart, attnh);

    // 11: G3: out = gelu([x | attn] @ [W_out1 | P2]^T + b_out) + x
    mma_gemm<7><<<dim3(D_DIM / 128, B / 128), 256, SMEM_SZ>>>(
        xh, attnh, wcomb, b_out, x, out,
        D_DIM, KCOMB, D_DIM, D_DIM, S_PROTO,
        nullptr, nullptr, nullptr, 0, 0x7FFFFFFF, nullptr);

    // 12: final LayerNorm
    layernorm_inplace<<<B, 256>>>(out, ln_w, ln_b);
}

// round 12
// speedup vs baseline: 1.0740x; 1.0390x over previous
#include <cuda_runtime.h>
#include <cuda_fp16.h>
#include <math.h>
#include <stdint.h>

#define B_ROWS 16384
#define D_DIM  2048
#define D_HALF 1024
#define S_PROTO 64
#define KCOMB  (D_DIM + S_PROTO)   // 2112

// ---------------------------------------------------------------------------
// Scratch (device globals; allocation-free per harness rules)
// ---------------------------------------------------------------------------
__device__ __half g_x_h[(size_t)B_ROWS * D_DIM];
__device__ __half g_Win_h[(size_t)D_DIM * D_DIM];
__device__ __half g_Wr1_h[(size_t)D_HALF * D_DIM];
__device__ __half g_wcomb[(size_t)D_DIM * KCOMB];      // [W_out1 | P2^T] fp16
__device__ __half g_attn_h[(size_t)B_ROWS * S_PROTO];
__device__ __half g_qp_h[(size_t)S_PROTO * D_DIM];     // q = pn @ W_in, fp16
__device__ float g_pn_f[(size_t)S_PROTO * D_DIM];      // normalized protos fp32
__device__ float g_p2part[4 * S_PROTO * D_DIM];
__device__ float g_qppart[8 * S_PROTO * D_DIM];
__device__ float g_ssqpart[16 * B_ROWS];               // per n-tile row ssq
__device__ float g_twpart[(size_t)B_ROWS * 32];        // [row][tile0..7][4]
__device__ float g_base[S_PROTO];
__device__ float g_wsimc[S_PROTO];

// ---------------------------------------------------------------------------
// PTX helpers (baseline ISA: mma.sync / ldmatrix / cp.async)
// ---------------------------------------------------------------------------
__device__ __forceinline__ uint32_t smem_to_u32(const void* p) {
    uint32_t a;
    asm("{ .reg .u64 t; cvta.to.shared.u64 t, %1; cvt.u32.u64 %0, t; }"
        : "=r"(a) : "l"(p));
    return a;
}

__device__ __forceinline__ void cpasync16(uint32_t saddr, const void* g) {
    asm volatile("cp.async.cg.shared.global [%0], [%1], 16;"
                 :: "r"(saddr), "l"(g));
}
#define CP_COMMIT() asm volatile("cp.async.commit_group;" ::: "memory")
#define CP_WAIT(n)  asm volatile("cp.async.wait_group %0;" :: "n"(n) : "memory")

__device__ __forceinline__ void ldsm4(uint32_t* r, uint32_t addr) {
    asm volatile("ldmatrix.sync.aligned.m8n8.x4.shared.b16 {%0,%1,%2,%3}, [%4];"
                 : "=r"(r[0]), "=r"(r[1]), "=r"(r[2]), "=r"(r[3]) : "r"(addr));
}

__device__ __forceinline__ void mma_f16(float* d, const uint32_t* a, const uint32_t* b) {
    asm volatile(
        "mma.sync.aligned.m16n8k16.row.col.f32.f16.f16.f32 "
        "{%0,%1,%2,%3}, {%4,%5,%6,%7}, {%8,%9}, {%0,%1,%2,%3};"
        : "+f"(d[0]), "+f"(d[1]), "+f"(d[2]), "+f"(d[3])
        : "r"(a[0]), "r"(a[1]), "r"(a[2]), "r"(a[3]), "r"(b[0]), "r"(b[1]));
}

// ---------------------------------------------------------------------------
// Misc helpers
// ---------------------------------------------------------------------------
__device__ __forceinline__ float gelu_exact(float v) {
    return 0.5f * v * (1.0f + erff(v * 0.70710678118654752440f));
}

__device__ __forceinline__ float block_reduce_sum(float v) {
    __shared__ float sh[32];
    int lane = threadIdx.x & 31, w = threadIdx.x >> 5;
    #pragma unroll
    for (int o = 16; o; o >>= 1) v += __shfl_xor_sync(0xFFFFFFFFu, v, o);
    if (lane == 0) sh[w] = v;
    __syncthreads();
    float r = (threadIdx.x < (blockDim.x >> 5)) ? sh[threadIdx.x] : 0.0f;
    if (w == 0) {
        #pragma unroll
        for (int o = 16; o; o >>= 1) r += __shfl_xor_sync(0xFFFFFFFFu, r, o);
        if (lane == 0) sh[0] = r;
    }
    __syncthreads();
    float out = sh[0];
    __syncthreads();
    return out;
}

// ---------------------------------------------------------------------------
// fp32 -> fp16 convert (vectorized, contiguous)
// ---------------------------------------------------------------------------
__global__ void tohalf_kernel(const float* __restrict__ s,
                              __half* __restrict__ d, size_t n4)
{
    size_t i = (size_t)blockIdx.x * blockDim.x + threadIdx.x;
    if (i >= n4) return;
    float4 v = reinterpret_cast<const float4*>(s)[i];
    __half2 h0 = __floats2half2_rn(v.x, v.y);
    __half2 h1 = __floats2half2_rn(v.z, v.w);
    uint2 o;
    o.x = *reinterpret_cast<uint32_t*>(&h0);
    o.y = *reinterpret_cast<uint32_t*>(&h1);
    reinterpret_cast<uint2*>(d)[i] = o;
}

// ---------------------------------------------------------------------------
// Pack W_out[:, 0:2048] (stride 4096) into wcomb[:, 0:2048] (stride 2112) fp16
// ---------------------------------------------------------------------------
__global__ void wout1_pack_kernel(const float* __restrict__ wout,
                                  __half* __restrict__ wcomb)
{
    int idx = blockIdx.x * 256 + threadIdx.x;
    int row = idx >> 9;
    int c4  = idx & 511;
    float4 v = *reinterpret_cast<const float4*>(wout + (size_t)row * 2 * D_DIM + c4 * 4);
    __half2 h0 = __floats2half2_rn(v.x, v.y);
    __half2 h1 = __floats2half2_rn(v.z, v.w);
    uint2 o;
    o.x = *reinterpret_cast<uint32_t*>(&h0);
    o.y = *reinterpret_cast<uint32_t*>(&h1);
    *reinterpret_cast<uint2*>(wcomb + (size_t)row * KCOMB + c4 * 4) = o;
}

// ---------------------------------------------------------------------------
// P2 partials (k-split, conflict-free transposed tiles)
// ---------------------------------------------------------------------------
__global__ void __launch_bounds__(256)
p2_kernel(const float* __restrict__ protos, const float* __restrict__ wout,
          float* __restrict__ part)
{
    constexpr int BKC = 32;
    __shared__ float Pt[BKC][68];
    __shared__ float Wt[BKC][132];

    const int tid = threadIdx.x;
    const int n0 = blockIdx.x * 128;
    const int kb = blockIdx.y * 512;
    const int tr = tid >> 4;
    const int tc = tid & 15;

    float acc[4][8];
    #pragma unroll
    for (int i = 0; i < 4; i++)
        #pragma unroll
        for (int j = 0; j < 8; j++) acc[i][j] = 0.0f;

    for (int kt = 0; kt < 512; kt += BKC) {
        #pragma unroll
        for (int i = 0; i < 2; i++) {
            int idx = tid + i * 256;
            int s = idx >> 3, kq = (idx & 7) * 4;
            float4 v = *reinterpret_cast<const float4*>(
                protos + (size_t)s * D_DIM + kb + kt + kq);
            Pt[kq+0][s] = v.x; Pt[kq+1][s] = v.y;
            Pt[kq+2][s] = v.z; Pt[kq+3][s] = v.w;
        }
        #pragma unroll
        for (int i = 0; i < 4; i++) {
            int idx = tid + i * 256;
            int n = idx >> 3, kq = (idx & 7) * 4;
            float4 v = *reinterpret_cast<const float4*>(
                wout + (size_t)(n0 + n) * 2 * D_DIM + D_DIM + kb + kt + kq);
            Wt[kq+0][n] = v.x; Wt[kq+1][n] = v.y;
            Wt[kq+2][n] = v.z; Wt[kq+3][n] = v.w;
        }
        __syncthreads();
        #pragma unroll 8
        for (int k = 0; k < BKC; k++) {
            float4 p  = *reinterpret_cast<const float4*>(&Pt[k][tr * 4]);
            float4 wa = *reinterpret_cast<const float4*>(&Wt[k][tc * 8]);
            float4 wb = *reinterpret_cast<const float4*>(&Wt[k][tc * 8 + 4]);
            float pv[4] = {p.x, p.y, p.z, p.w};
            float wv[8] = {wa.x, wa.y, wa.z, wa.w, wb.x, wb.y, wb.z, wb.w};
            #pragma unroll
            for (int i = 0; i < 4; i++)
                #pragma unroll
                for (int j = 0; j < 8; j++)
                    acc[i][j] = fmaf(pv[i], wv[j], acc[i][j]);
        }
        __syncthreads();
    }

    float* dst = part + (size_t)blockIdx.y * S_PROTO * D_DIM;
    #pragma unroll
    for (int i = 0; i < 4; i++)
        #pragma unroll
        for (int j = 0; j < 8; j++)
            dst[(size_t)(tr * 4 + i) * D_DIM + n0 + tc * 8 + j] = acc[i][j];
}

// ---------------------------------------------------------------------------
// qp partials: part[ks][s][d] = sum_{j in slice} pn[s][j] * Win[j][d]
// ---------------------------------------------------------------------------
__global__ void __launch_bounds__(256)
qp_kernel(const float* __restrict__ pnf, const float* __restrict__ win,
          float* __restrict__ part)
{
    constexpr int BKC = 32;
    __shared__ float Pt[BKC][68];
    __shared__ float Wt[BKC][132];

    const int tid = threadIdx.x;
    const int n0 = blockIdx.x * 128;
    const int kb = blockIdx.y * 256;
    const int tr = tid >> 4;
    const int tc = tid & 15;

    float acc[4][8];
    #pragma unroll
    for (int i = 0; i < 4; i++)
        #pragma unroll
        for (int j = 0; j < 8; j++) acc[i][j] = 0.0f;

    for (int kt = 0; kt < 256; kt += BKC) {
        #pragma unroll
        for (int i = 0; i < 2; i++) {
            int idx = tid + i * 256;
            int s = idx >> 3, jq = (idx & 7) * 4;
            float4 v = *reinterpret_cast<const float4*>(
                pnf + (size_t)s * D_DIM + kb + kt + jq);
            Pt[jq+0][s] = v.x; Pt[jq+1][s] = v.y;
            Pt[jq+2][s] = v.z; Pt[jq+3][s] = v.w;
        }
        #pragma unroll
        for (int i = 0; i < 4; i++) {
            int idx = tid + i * 256;
            int j = idx >> 5, d4 = idx & 31;
            float4 v = *reinterpret_cast<const float4*>(
                win + (size_t)(kb + kt + j) * D_DIM + n0 + d4 * 4);
            Wt[j][d4*4+0] = v.x; Wt[j][d4*4+1] = v.y;
            Wt[j][d4*4+2] = v.z; Wt[j][d4*4+3] = v.w;
        }
        __syncthreads();
        #pragma unroll 8
        for (int k = 0; k < BKC; k++) {
            float4 p  = *reinterpret_cast<const float4*>(&Pt[k][tr * 4]);
            float4 wa = *reinterpret_cast<const float4*>(&Wt[k][tc * 8]);
            float4 wb = *reinterpret_cast<const float4*>(&Wt[k][tc * 8 + 4]);
            float pv[4] = {p.x, p.y, p.z, p.w};
            float wv[8] = {wa.x, wa.y, wa.z, wa.w, wb.x, wb.y, wb.z, wb.w};
            #pragma unroll
            for (int i = 0; i < 4; i++)
                #pragma unroll
                for (int j = 0; j < 8; j++)
                    acc[i][j] = fmaf(pv[i], wv[j], acc[i][j]);
        }
        __syncthreads();
    }

    float* dst = part + (size_t)blockIdx.y * S_PROTO * D_DIM;
    #pragma unroll
    for (int i = 0; i < 4; i++)
        #pragma unroll
        for (int j = 0; j < 8; j++)
            dst[(size_t)(tr * 4 + i) * D_DIM + n0 + tc * 8 + j] = acc[i][j];
}

// ---------------------------------------------------------------------------
// Combined reduce: blocks [0,512) -> qp (8-way) -> qph;
//                  blocks [512,1024) -> p2 (4-way) -> wcomb tail.
// ---------------------------------------------------------------------------
__global__ void prep_reduce_kernel(const float* __restrict__ qppart,
                                   const float* __restrict__ p2part,
                                   __half* __restrict__ qph,
                                   __half* __restrict__ wcomb)
{
    int b = blockIdx.x;
    if (b < 512) {
        int idx = b * 256 + threadIdx.x;
        float v = 0.0f;
        #pragma unroll
        for (int t = 0; t < 8; t++) v += qppart[(size_t)t * S_PROTO * D_DIM + idx];
        qph[idx] = __float2half_rn(v);
    } else {
        int idx = (b - 512) * 256 + threadIdx.x;
        int s = idx >> 11;
        int n = idx & 2047;
        size_t o = (size_t)s * D_DIM + n;
        float v = p2part[o] + p2part[o + S_PROTO * D_DIM]
                + p2part[o + 2 * S_PROTO * D_DIM] + p2part[o + 3 * S_PROTO * D_DIM];
        wcomb[(size_t)n * KCOMB + D_DIM + s] = __float2half_rn(v);
    }
}

// ---------------------------------------------------------------------------
// Single-pass fp16 HMMA GEMM.
// MODE bits: 1=gelu, 2=+Xres(fp32), 4=split-A, 8=dual-output,
//            16=fp16 C outputs, 32=first-output is row-ssq (no C write),
//            64=second-output emits tw partials (r never stored).
// BM=BN=128, BK=64, 3-stage cp.async, 256 threads, 2 CTAs/SM.
// ---------------------------------------------------------------------------
template<int MODE>
__global__ void __launch_bounds__(256, 2)
mma_gemm(const __half* __restrict__ A, const __half* __restrict__ A2,
         const __half* __restrict__ Bm,
         const float* __restrict__ bias, const float* __restrict__ Xres,
         void* __restrict__ C, int N, int K, int Ksplit,
         int strideA, int strideA2,
         const __half* __restrict__ B2,
         const float* __restrict__ bias2, void* __restrict__ C2,
         int N2, int NXtiles, float* __restrict__ ssqpart,
         const float* __restrict__ Wr2, float* __restrict__ twpart)
{
    constexpr int BM = 128, BK = 64, STAGES = 3;
    constexpr int TILE_B  = BM * BK * 2;
    constexpr int STAGE_B = 2 * TILE_B;

    extern __shared__ __align__(16) char smem[];
    const uint32_t sbase = smem_to_u32(smem);

    const int tid  = threadIdx.x;
    const int wid  = tid >> 5, lane = tid & 31;
    const int m0 = blockIdx.y * BM;

    int bx = blockIdx.x;
    bool second = false;
    if constexpr (MODE & 8) {
        if (bx >= NXtiles) { second = true; bx -= NXtiles; }
    }
    const __half* pB = second ? B2 : Bm;
    const float* pbias = second ? bias2 : bias;
    void* pC = second ? C2 : C;
    const int NN = second ? N2 : N;
    const int n0 = bx * BM;
    const bool do_gelu = (MODE & 1) || second;

    const int wm = (wid >> 2) * 64;
    const int wn = (wid & 3) * 32;

    float acc[4][4][4];
    #pragma unroll
    for (int i = 0; i < 4; i++)
        #pragma unroll
        for (int j = 0; j < 4; j++)
            #pragma unroll
            for (int k = 0; k < 4; k++) acc[i][j][k] = 0.0f;

    const int nk = K / BK;

    // --- incremental per-thread load pointers ---
    const int rowb = tid >> 3;
    const int gld  = tid & 7;
    const uint32_t sw_base = rowb * 128 + ((gld ^ (rowb & 7)) * 16);
    const __half* pAp = A + (size_t)(m0 + rowb) * strideA + gld * 8;
    const __half* pBp = pB + (size_t)(n0 + rowb) * K + gld * 8;
    int sAcur = strideA;
    const int kswitch = (MODE & 4) ? (Ksplit / BK) : 0x7FFFFFFF;

    auto load_stage = [&](int s, int t) {
        if constexpr (MODE & 4) {
            if (t == kswitch) {
                pAp = A2 + (size_t)(m0 + rowb) * strideA2 + gld * 8;
                sAcur = strideA2;
            }
        }
        const uint32_t sb = sbase + s * STAGE_B;
        #pragma unroll
        for (int i = 0; i < 4; i++) {
            uint32_t so = sb + sw_base + i * (32 * 128);
            cpasync16(so, pAp + (size_t)i * 32 * sAcur);
            cpasync16(so + TILE_B, pBp + (size_t)i * 32 * K);
        }
        pAp += BK; pBp += BK;
    };

    // --- hoisted LDSM swizzle bases ---
    const uint32_t r7 = (uint32_t)(lane & 7);
    const uint32_t gaH = (uint32_t)(lane >> 4);
    const uint32_t gbH = (uint32_t)((lane >> 3) & 1);
    uint32_t abase[4], bbase[2];
    #pragma unroll
    for (int mf = 0; mf < 4; mf++)
        abase[mf] = (uint32_t)(wm + mf * 16 + (lane & 15)) * 128;
    #pragma unroll
    for (int nf2 = 0; nf2 < 2; nf2++)
        bbase[nf2] = TILE_B +
            (uint32_t)(wn + nf2 * 16 + ((lane >> 4) & 1) * 8 + (lane & 7)) * 128;

    auto compute_stage = [&](int s) {
        const uint32_t sb = sbase + s * STAGE_B;
        #pragma unroll
        for (int ks = 0; ks < 4; ks++) {
            const uint32_t gA = ((ks * 2 + gaH) ^ r7) << 4;
            const uint32_t gB = ((ks * 2 + gbH) ^ r7) << 4;
            uint32_t afr[4][4], bfr[2][4];
            #pragma unroll
            for (int mf = 0; mf < 4; mf++)
                ldsm4(afr[mf], sb + abase[mf] + gA);
            #pragma unroll
            for (int nf2 = 0; nf2 < 2; nf2++)
                ldsm4(bfr[nf2], sb + bbase[nf2] + gB);
            #pragma unroll
            for (int mf = 0; mf < 4; mf++)
                #pragma unroll
                for (int nf = 0; nf < 4; nf++)
                    mma_f16(acc[mf][nf], afr[mf], &bfr[nf >> 1][(nf & 1) * 2]);
        }
    };

    load_stage(0, 0); CP_COMMIT();
    load_stage(1, 1); CP_COMMIT();

    for (int t = 0; t < nk; t++) {
        CP_WAIT(STAGES - 2);
        __syncthreads();
        if (t + STAGES - 1 < nk) load_stage((t + STAGES - 1) % STAGES, t + STAGES - 1);
        CP_COMMIT();
        compute_stage(t % STAGES);
    }

    bool ssq_mode = false;
    if constexpr (MODE & 32) ssq_mode = !second;
    bool tw_mode = false;
    if constexpr (MODE & 64) tw_mode = second;

    if (ssq_mode) {
        float rs[4][2];
        #pragma unroll
        for (int mf = 0; mf < 4; mf++)
            #pragma unroll
            for (int half = 0; half < 2; half++) {
                float s = 0.0f;
                #pragma unroll
                for (int nf = 0; nf < 4; nf++)
                    #pragma unroll
                    for (int k = 0; k < 2; k++) {
                        int col = n0 + wn + nf * 8 + (lane & 3) * 2 + k;
                        float v = acc[mf][nf][half * 2 + k] + pbias[col];
                        s = fmaf(v, v, s);
                    }
                rs[mf][half] = s;
            }
        #pragma unroll
        for (int mf = 0; mf < 4; mf++)
            #pragma unroll
            for (int half = 0; half < 2; half++) {
                rs[mf][half] += __shfl_xor_sync(0xFFFFFFFFu, rs[mf][half], 1);
                rs[mf][half] += __shfl_xor_sync(0xFFFFFFFFu, rs[mf][half], 2);
            }
        __syncthreads();
        float* ssqsm = reinterpret_cast<float*>(smem);
        if ((lane & 3) == 0) {
            #pragma unroll
            for (int mf = 0; mf < 4; mf++)
                #pragma unroll
                for (int half = 0; half < 2; half++)
                    ssqsm[wid * 64 + mf * 16 + (lane >> 2) + half * 8] = rs[mf][half];
        }
        __syncthreads();
        if (tid < 128) {
            int group = tid >> 6, r = tid & 63;
            float v = ssqsm[(group * 4 + 0) * 64 + r]
                    + ssqsm[(group * 4 + 1) * 64 + r]
                    + ssqsm[(group * 4 + 2) * 64 + r]
                    + ssqsm[(group * 4 + 3) * 64 + r];
            ssqpart[(size_t)bx * B_ROWS + m0 + group * 64 + r] = v;
        }
    } else if (tw_mode) {
        // r tile (post-gelu) dotted against Wr2[4][1024] slice -> tw partials
        float tp[4][2][4];   // [mf][half][logit]
        #pragma unroll
        for (int mf = 0; mf < 4; mf++)
            #pragma unroll
            for (int half = 0; half < 2; half++) {
                float p0 = 0.f, p1 = 0.f, p2 = 0.f, p3 = 0.f;
                #pragma unroll
                for (int nf = 0; nf < 4; nf++)
                    #pragma unroll
                    for (int k = 0; k < 2; k++) {
                        int col = n0 + wn + nf * 8 + (lane & 3) * 2 + k;
                        float v = gelu_exact(acc[mf][nf][half * 2 + k] + pbias[col]);
                        p0 = fmaf(v, Wr2[0 * D_HALF + col], p0);
                        p1 = fmaf(v, Wr2[1 * D_HALF + col], p1);
                        p2 = fmaf(v, Wr2[2 * D_HALF + col], p2);
                        p3 = fmaf(v, Wr2[3 * D_HALF + col], p3);
                    }
                tp[mf][half][0] = p0; tp[mf][half][1] = p1;
                tp[mf][half][2] = p2; tp[mf][half][3] = p3;
            }
        #pragma unroll
        for (int mf = 0; mf < 4; mf++)
            #pragma unroll
            for (int half = 0; half < 2; half++)
                #pragma unroll
                for (int t = 0; t < 4; t++) {
                    tp[mf][half][t] += __shfl_xor_sync(0xFFFFFFFFu, tp[mf][half][t], 1);
                    tp[mf][half][t] += __shfl_xor_sync(0xFFFFFFFFu, tp[mf][half][t], 2);
                }
        __syncthreads();
        float (*twsm)[128][4] = reinterpret_cast<float (*)[128][4]>(smem);
        if ((lane & 3) == 0) {
            #pragma unroll
            for (int mf = 0; mf < 4; mf++)
                #pragma unroll
                for (int half = 0; half < 2; half++) {
                    int row = wm + mf * 16 + (lane >> 2) + half * 8;
                    #pragma unroll
                    for (int t = 0; t < 4; t++)
                        twsm[wid & 3][row][t] = tp[mf][half][t];
                }
        }
        __syncthreads();
        if (tid < 128) {
            #pragma unroll
            for (int t = 0; t < 4; t++) {
                float z = twsm[0][tid][t] + twsm[1][tid][t]
                        + twsm[2][tid][t] + twsm[3][tid][t];
                twpart[(size_t)(m0 + tid) * 32 + bx * 4 + t] = z;
            }
        }
    } else {
        #pragma unroll
        for (int mf = 0; mf < 4; mf++)
            #pragma unroll
            for (int nf = 0; nf < 4; nf++)
                #pragma unroll
                for (int half = 0; half < 2; half++) {
                    int row = m0 + wm + mf * 16 + (lane >> 2) + half * 8;
                    int col = n0 + wn + nf * 8 + (lane & 3) * 2;
                    float v0 = acc[mf][nf][half * 2 + 0] + pbias[col];
                    float v1 = acc[mf][nf][half * 2 + 1] + pbias[col + 1];
                    if (do_gelu) { v0 = gelu_exact(v0); v1 = gelu_exact(v1); }
                    if constexpr (MODE & 2) {
                        float2 xr = *reinterpret_cast<const float2*>(
                            &Xres[(size_t)row * NN + col]);
                        v0 += xr.x; v1 += xr.y;
                    }
                    if constexpr (MODE & 16) {
                        __half2 o = __floats2half2_rn(v0, v1);
                        *reinterpret_cast<__half2*>(
                            (__half*)pC + (size_t)row * NN + col) = o;
                    } else {
                        float2 o; o.x = v0; o.y = v1;
                        *reinterpret_cast<float2*>(
                            (float*)pC + (size_t)row * NN + col) = o;
                    }
                }
    }
}

// ---------------------------------------------------------------------------
// sim_attn v5: fused invn + tw (from partials) + HMMA sim + salience + softmax
// -> attn fp16. 128 rows/block, 256 threads.
// ---------------------------------------------------------------------------
__global__ void __launch_bounds__(256)
sim_attn_kernel(const __half* __restrict__ X, const __half* __restrict__ QP,
                const float* __restrict__ twpart, const float* __restrict__ br2,
                const float* __restrict__ ssqpart, __half* __restrict__ attn)
{
    constexpr int BK = 64;
    constexpr int H_B  = 128 * BK * 2;
    constexpr int PN_B = S_PROTO * BK * 2;
    constexpr int STAGE_B = H_B + PN_B;
    constexpr int INVN_OFF = 2 * STAGE_B;        // 49152
    constexpr int TW_OFF   = INVN_OFF + 512;     // 49664

    extern __shared__ __align__(16) char dsm[];
    const uint32_t sbase = smem_to_u32(dsm);
    float* sal = reinterpret_cast<float*>(dsm);
    float* invn_sm = reinterpret_cast<float*>(dsm + INVN_OFF);
    float* tw_sm = reinterpret_cast<float*>(dsm + TW_OFF);   // [128][4]

    const int tid = threadIdx.x;
    const int wid = tid >> 5, lane = tid & 31;
    const int m0 = blockIdx.x * 128;
    const int K = D_DIM;

    // fused invn + type-weight softmax (per row)
    if (tid < 128) {
        float s = 0.0f;
        #pragma unroll
        for (int t = 0; t < 16; t++) s += ssqpart[(size_t)t * B_ROWS + m0 + tid];
        invn_sm[tid] = 1.0f / fmaxf(sqrtf(s), 1e-12f);

        const float* tp = twpart + (size_t)(m0 + tid) * 32;
        float z[4];
        #pragma unroll
        for (int t = 0; t < 4; t++) z[t] = br2[t];
        #pragma unroll
        for (int tile = 0; tile < 8; tile++)
            #pragma unroll
            for (int t = 0; t < 4; t++) z[t] += tp[tile * 4 + t];
        float m = fmaxf(fmaxf(z[0], z[1]), fmaxf(z[2], z[3]));
        float e0 = expf(z[0] - m), e1 = expf(z[1] - m);
        float e2 = expf(z[2] - m), e3 = expf(z[3] - m);
        float inv = 1.0f / (e0 + e1 + e2 + e3);
        tw_sm[tid * 4 + 0] = e0 * inv; tw_sm[tid * 4 + 1] = e1 * inv;
        tw_sm[tid * 4 + 2] = e2 * inv; tw_sm[tid * 4 + 3] = e3 * inv;
    }

    float acc[8][4];
    #pragma unroll
    for (int i = 0; i < 8; i++)
        #pragma unroll
        for (int j = 0; j < 4; j++) acc[i][j] = 0.0f;

    uint4 hReg[4]; uint4 pReg[2];

    auto fetch = [&](int t) {
        const int k0 = t * BK;
        #pragma unroll
        for (int i = 0; i < 4; i++) {
            int idx = tid + i * 256;
            int row = idx >> 3, g = idx & 7;
            hReg[i] = *reinterpret_cast<const uint4*>(
                X + (size_t)(m0 + row) * K + k0 + g * 8);
        }
        #pragma unroll
        for (int i = 0; i < 2; i++) {
            int idx = tid + i * 256;
            int s = idx >> 3, g = idx & 7;
            pReg[i] = *reinterpret_cast<const uint4*>(
                QP + (size_t)s * K + k0 + g * 8);
        }
    };
    auto stash = [&](int buf) {
        char* cb = dsm + buf * STAGE_B;
        #pragma unroll
        for (int i = 0; i < 4; i++) {
            int idx = tid + i * 256;
            int row = idx >> 3, g = idx & 7;
            *reinterpret_cast<uint4*>(cb + row * 128 + ((g ^ (row & 7)) * 16)) = hReg[i];
        }
        #pragma unroll
        for (int i = 0; i < 2; i++) {
            int idx = tid + i * 256;
            int s = idx >> 3, g = idx & 7;
            *reinterpret_cast<uint4*>(cb + H_B + s * 128 + ((g ^ (s & 7)) * 16)) = pReg[i];
        }
    };
    auto compute = [&](int buf) {
        const uint32_t sb = sbase + buf * STAGE_B;
        #pragma unroll
        for (int ks = 0; ks < 4; ks++) {
            uint32_t afr[4], bfr[4][4];
            {
                int row = wid * 16 + (lane & 15);
                int g   = ks * 2 + (lane >> 4);
                ldsm4(afr, sb + row * 128 + ((g ^ (row & 7)) * 16));
            }
            #pragma unroll
            for (int nf2 = 0; nf2 < 4; nf2++) {
                int nrow = nf2 * 16 + ((lane >> 4) & 1) * 8 + (lane & 7);
                int g    = ks * 2 + ((lane >> 3) & 1);
                ldsm4(bfr[nf2], sb + H_B + nrow * 128 + ((g ^ (nrow & 7)) * 16));
            }
            #pragma unroll
            for (int nf = 0; nf < 8; nf++)
                mma_f16(acc[nf], afr, &bfr[nf >> 1][(nf & 1) * 2]);
        }
    };

    const int nk = K / BK;
    fetch(0); stash(0);
    __syncthreads();
    for (int t = 0; t < nk; t++) {
        const int cur = t & 1;
        if (t + 1 < nk) fetch(t + 1);
        compute(cur);
        if (t + 1 < nk) stash(cur ^ 1);
        __syncthreads();
    }

    // salience into smem (overlay; invn/tw regions untouched)
    {
        int r0 = wid * 16 + (lane >> 2);
        #pragma unroll
        for (int half = 0; half < 2; half++) {
            int row = r0 + half * 8;
            float invn = invn_sm[row];
            #pragma unroll
            for (int nf = 0; nf < 8; nf++) {
                int col = nf * 8 + (lane & 3) * 2;
                float twv = tw_sm[row * 4 + (col >> 4)];
                float v0 = g_wsimc[col] * twv * (acc[nf][half*2+0] * invn) + g_base[col];
                float v1 = g_wsimc[col+1] * twv * (acc[nf][half*2+1] * invn) + g_base[col+1];
                sal[row * 65 + col]     = fminf(fmaxf(v0, 0.0f), 1.0f);
                sal[row * 65 + col + 1] = fminf(fmaxf(v1, 0.0f), 1.0f);
            }
        }
    }
    __syncthreads();

    // softmax over 64 per row; 2 threads per row
    {
        int row = tid >> 1, half = tid & 1;
        const float* srow = &sal[row * 65 + half * 32];
        float m = -1e30f;
        #pragma unroll
        for (int c = 0; c < 32; c++) m = fmaxf(m, srow[c]);
        m = fmaxf(m, __shfl_xor_sync(0xFFFFFFFFu, m, 1));
        const float invT = 1.0f / 0.07f;
        float e[32], s = 0.0f;
        #pragma unroll
        for (int c = 0; c < 32; c++) { e[c] = expf((srow[c] - m) * invT); s += e[c]; }
        s += __shfl_xor_sync(0xFFFFFFFFu, s, 1);
        float inv = 1.0f / s;
        __half* dst = &attn[(size_t)(m0 + row) * S_PROTO + half * 32];
        #pragma unroll
        for (int c = 0; c < 32; c += 2) {
            __half2 o = __floats2half2_rn(e[c] * inv, e[c+1] * inv);
            *reinterpret_cast<__half2*>(dst + c) = o;
        }
    }
}

// ---------------------------------------------------------------------------
// Prototype prep: normalized protos -> fp32, plus static salience terms
// ---------------------------------------------------------------------------
__global__ void proto_prep(const float* __restrict__ protos,
                           const float* __restrict__ conf,
                           const float* __restrict__ age,
                           const float* __restrict__ ev,
                           float* __restrict__ pn_f)
{
    const int s = blockIdx.x;
    float ss = 0.0f;
    for (int k = threadIdx.x; k < D_DIM; k += 256) {
        float v = protos[(size_t)s * D_DIM + k];
        ss += v * v;
    }
    float tot = block_reduce_sum(ss);
    float scale = 1.0f / fmaxf(sqrtf(tot), 1e-12f);
    for (int k = threadIdx.x; k < D_DIM; k += 256)
        pn_f[(size_t)s * D_DIM + k] = protos[(size_t)s * D_DIM + k] * scale;

    if (threadIdx.x == 0) {
        float evmax = 0.0f;
        for (int i = 0; i < S_PROTO; i++) evmax = fmaxf(evmax, ev[i]);
        float freq = logf(ev[s] + 1.0f) / (logf(evmax + 2.0f) + 1e-8f);
        float rec  = expf(-age[s] * (1.0f / 200.0f));
        g_base[s]  = 0.2f * rec + 0.15f * freq + 0.1f * conf[s] + 0.1f * 0.9f;
        g_wsimc[s] = 0.45f * conf[s];
    }
}

// ---------------------------------------------------------------------------
// In-place LayerNorm over D
// ---------------------------------------------------------------------------
__global__ void layernorm_inplace(float* __restrict__ y,
                                  const float* __restrict__ w,
                                  const float* __restrict__ bb)
{
    const size_t base = (size_t)blockIdx.x * D_DIM;
    float4* yp = reinterpret_cast<float4*>(y + base);
    float4 v[2];
    float sum = 0.0f;
    #pragma unroll
    for (int i = 0; i < 2; i++) {
        v[i] = yp[threadIdx.x + 256 * i];
        sum += v[i].x + v[i].y + v[i].z + v[i].w;
    }
    float mu = block_reduce_sum(sum) * (1.0f / D_DIM);
    float sq = 0.0f;
    #pragma unroll
    for (int i = 0; i < 2; i++) {
        float dx = v[i].x - mu, dy = v[i].y - mu, dz = v[i].z - mu, dw = v[i].w - mu;
        sq += dx*dx + dy*dy + dz*dz + dw*dw;
    }
    float var = block_reduce_sum(sq) * (1.0f / D_DIM);
    float rstd = rsqrtf(var + 1e-5f);
    #pragma unroll
    for (int i = 0; i < 2; i++) {
        int col = (threadIdx.x + 256 * i) * 4;
        float4 wv = *reinterpret_cast<const float4*>(&w[col]);
        float4 bv = *reinterpret_cast<const float4*>(&bb[col]);
        float4 o;
        o.x = wv.x * (v[i].x - mu) * rstd + bv.x;
        o.y = wv.y * (v[i].y - mu) * rstd + bv.y;
        o.z = wv.z * (v[i].z - mu) * rstd + bv.z;
        o.w = wv.w * (v[i].w - mu) * rstd + bv.w;
        yp[threadIdx.x + 256 * i] = o;
    }
}

// ---------------------------------------------------------------------------
// Launch
// ---------------------------------------------------------------------------
extern "C" void kernel_launch(void* const* d_in, const int* in_sizes, int n_in,
                              void* d_out, int out_size)
{
    const float* x      = (const float*)d_in[0];
    const float* protos = (const float*)d_in[1];
    const float* conf   = (const float*)d_in[2];
    const float* age    = (const float*)d_in[3];
    const float* ev     = (const float*)d_in[4];
    const float* W_in   = (const float*)d_in[5];
    const float* b_in   = (const float*)d_in[6];
    const float* Wr1    = (const float*)d_in[7];
    const float* br1    = (const float*)d_in[8];
    const float* Wr2    = (const float*)d_in[9];
    const float* br2    = (const float*)d_in[10];
    const float* W_out  = (const float*)d_in[11];
    const float* b_out  = (const float*)d_in[12];
    const float* ln_w   = (const float*)d_in[13];
    const float* ln_b   = (const float*)d_in[14];
    float* out = (float*)d_out;

    __half *xh, *winh, *wr1h, *wcomb, *attnh, *qph;
    float *p2part, *qppart, *pnf, *ssqpart, *twpart;
    cudaGetSymbolAddress((void**)&xh,    g_x_h);
    cudaGetSymbolAddress((void**)&winh,  g_Win_h);
    cudaGetSymbolAddress((void**)&wr1h,  g_Wr1_h);
    cudaGetSymbolAddress((void**)&wcomb, g_wcomb);
    cudaGetSymbolAddress((void**)&attnh, g_attn_h);
    cudaGetSymbolAddress((void**)&qph,   g_qp_h);
    cudaGetSymbolAddress((void**)&pnf,   g_pn_f);
    cudaGetSymbolAddress((void**)&p2part, g_p2part);
    cudaGetSymbolAddress((void**)&qppart, g_qppart);
    cudaGetSymbolAddress((void**)&ssqpart, g_ssqpart);
    cudaGetSymbolAddress((void**)&twpart, g_twpart);

    constexpr int SMEM_SZ = 3 * 2 * 128 * 64 * 2;   // 98304
    constexpr int SIM_SMEM = 49152 + 512 + 2048;    // stages + invn + tw
    cudaFuncSetAttribute(mma_gemm<104>, cudaFuncAttributeMaxDynamicSharedMemorySize, SMEM_SZ);
    cudaFuncSetAttribute(mma_gemm<7>,   cudaFuncAttributeMaxDynamicSharedMemorySize, SMEM_SZ);
    cudaFuncSetAttribute(sim_attn_kernel, cudaFuncAttributeMaxDynamicSharedMemorySize, SIM_SMEM);

    const int B = B_ROWS;
    size_t n4;

    // 0-2: fp16 conversions
    n4 = (size_t)B * D_DIM / 4;
    tohalf_kernel<<<(unsigned)((n4 + 255) / 256), 256>>>(x, xh, n4);
    n4 = (size_t)D_DIM * D_DIM / 4;
    tohalf_kernel<<<(unsigned)((n4 + 255) / 256), 256>>>(W_in, winh, n4);
    n4 = (size_t)D_HALF * D_DIM / 4;
    tohalf_kernel<<<(unsigned)((n4 + 255) / 256), 256>>>(Wr1, wr1h, n4);

    // 3: G1+G2 fused (G1 -> ssq partials; G2 -> tw partials, r never stored)
    mma_gemm<104><<<dim3(D_DIM / 128 + D_HALF / 128, B / 128), 256, SMEM_SZ>>>(
        xh, nullptr, winh, b_in, nullptr, nullptr,
        D_DIM, D_DIM, 0, D_DIM, 0,
        wr1h, br1, nullptr, D_HALF, D_DIM / 128, ssqpart, Wr2, twpart);

    // 4: prototype normalization + static salience terms
    proto_prep<<<S_PROTO, 256>>>(protos, conf, age, ev, pnf);

    // 5: pack W_out1 into wcomb
    wout1_pack_kernel<<<(D_DIM * D_DIM / 4) / 256, 256>>>(W_out, wcomb);

    // 6-7: qp partials; P2 partials
    qp_kernel<<<dim3(D_DIM / 128, 8), 256>>>(pnf, W_in, qppart);
    p2_kernel<<<dim3(D_DIM / 128, 4), 256>>>(protos, W_out, p2part);

    // 8: combined reduce
    prep_reduce_kernel<<<1024, 256>>>(qppart, p2part, qph, wcomb);

    // 9: fused invn + tw-softmax + sim + salience + softmax -> attn
    sim_attn_kernel<<<B / 128, 256, SIM_SMEM>>>(xh, qph, twpart, br2, ssqpart, attnh);

    // 10: G3: out = gelu([x | attn] @ [W_out1 | P2]^T + b_out) + x
    mma_gemm<7><<<dim3(D_DIM / 128, B / 128), 256, SMEM_SZ>>>(
        xh, attnh, wcomb, b_out, x, out,
        D_DIM, KCOMB, D_DIM, D_DIM, S_PROTO,
        nullptr, nullptr, nullptr, 0, 0x7FFFFFFF, nullptr, nullptr, nullptr);

    // 11: final LayerNorm
    layernorm_inplace<<<B, 256>>>(out, ln_w, ln_b);
}